// round 2
// baseline (speedup 1.0000x reference)
#include <cuda_runtime.h>
#include <cuda_bf16.h>
#include <math.h>

#define N_NODES 50000
#define E_EDGES 800000
#define ETOT (E_EDGES + N_NODES)
#define CH 128
#define HEADS 4
#define HD 32
#define NEG_SLOPE 0.2f
#define BN_EPS 1e-5f

// ---------------- scratch (static device globals; no allocations) -------------
__device__ float  g_xl[(size_t)N_NODES * CH];
__device__ float  g_xr[(size_t)N_NODES * CH];
__device__ float  g_pre[(size_t)N_NODES * CH];
__device__ int    g_deg[N_NODES];
__device__ int    g_cur[N_NODES];
__device__ int    g_offs[N_NODES + 1];
__device__ int    g_src[ETOT];
__device__ float4 g_score[ETOT];
__device__ float  g_sum[CH];
__device__ float  g_sumsq[CH];
__device__ int    g_shift;   // 0: edge_index stored as int32; 1: int64 (read low word)

// ---------------- detect edge_index dtype --------------------------------------
// For int64 little-endian data, int32 words at odd indices are high words == 0
// (indices are < 2^31, non-negative). For int32 data they are random node ids.
__global__ void detect_k(const int* __restrict__ ei32) {
    __shared__ int any_nz;
    if (threadIdx.x == 0) any_nz = 0;
    __syncthreads();
    if (ei32[2 * threadIdx.x + 1] != 0) atomicOr(&any_nz, 1);
    __syncthreads();
    if (threadIdx.x == 0) g_shift = any_nz ? 0 : 1;
}

// ---------------- init: zero counters & stats ---------------------------------
__global__ void init_k() {
    int i = blockIdx.x * blockDim.x + threadIdx.x;
    if (i < N_NODES) { g_deg[i] = 0; g_cur[i] = 0; }
    if (i < CH) { g_sum[i] = 0.f; g_sumsq[i] = 0.f; }
}

// ---------------- fused GEMM: x_l = xW_l + b_l ; x_r = xW_r + b_r -------------
__global__ void gemm_k(const float* __restrict__ x,
                       const float* __restrict__ Wl, const float* __restrict__ bl,
                       const float* __restrict__ Wr, const float* __restrict__ br,
                       int n) {
    __shared__ float4 xs[32][32];   // 32 nodes x 128 ch (as float4)
    int t = threadIdx.x;
    int node0 = blockIdx.x * 32;
    #pragma unroll
    for (int q = 0; q < 4; q++) {
        int lin = t + q * 256;
        int r = lin >> 5, c4 = lin & 31;
        float4 v = make_float4(0.f, 0.f, 0.f, 0.f);
        if (node0 + r < n) v = ((const float4*)x)[(size_t)(node0 + r) * 32 + c4];
        xs[r][c4] = v;
    }
    __syncthreads();

    int c = t;
    const float* Wp;
    float bias;
    float* outp;
    if (c < CH) { Wp = Wl + c; bias = bl[c]; outp = g_xl; }
    else        { Wp = Wr + (c - CH); bias = br[c - CH]; outp = g_xr; }
    int cc = c & (CH - 1);

    float acc[32];
    #pragma unroll
    for (int i = 0; i < 32; i++) acc[i] = bias;

    for (int k4 = 0; k4 < 32; k4++) {
        float w0 = Wp[(k4 * 4 + 0) * CH];
        float w1 = Wp[(k4 * 4 + 1) * CH];
        float w2 = Wp[(k4 * 4 + 2) * CH];
        float w3 = Wp[(k4 * 4 + 3) * CH];
        #pragma unroll
        for (int i = 0; i < 32; i++) {
            float4 xv = xs[i][k4];
            acc[i] = fmaf(xv.x, w0, fmaf(xv.y, w1, fmaf(xv.z, w2, fmaf(xv.w, w3, acc[i]))));
        }
    }
    #pragma unroll
    for (int i = 0; i < 32; i++) {
        if (node0 + i < n) outp[(size_t)(node0 + i) * CH + cc] = acc[i];
    }
}

// ---------------- degree histogram (E real edges + N self loops) --------------
__global__ void hist_k(const int* __restrict__ ei32, int E, int n) {
    int i = blockIdx.x * blockDim.x + threadIdx.x;
    if (i >= E + n) return;
    int sh = g_shift;
    int d = (i < E) ? ei32[(size_t)(E + i) << sh] : (i - E);
    if (d >= 0 && d < n) atomicAdd(&g_deg[d], 1);
}

// ---------------- exclusive scan of degrees (single block, 1024 threads) ------
__global__ void scan_k(int n) {
    __shared__ int ssum[1024];
    int t = threadIdx.x;
    int C = (n + 1023) >> 10;
    int beg = t * C;
    int end = beg + C; if (end > n) end = n;
    int s = 0;
    for (int i = beg; i < end; i++) s += g_deg[i];
    ssum[t] = s;
    __syncthreads();
    for (int d = 1; d < 1024; d <<= 1) {
        int v = (t >= d) ? ssum[t - d] : 0;
        __syncthreads();
        ssum[t] += v;
        __syncthreads();
    }
    int run = (t > 0) ? ssum[t - 1] : 0;
    for (int i = beg; i < end; i++) { g_offs[i] = run; run += g_deg[i]; }
    if (t == 1023) g_offs[n] = ssum[1023];
}

// ---------------- scatter edges into CSR-by-dst order -------------------------
__global__ void scatter_k(const int* __restrict__ ei32, int E, int n) {
    int i = blockIdx.x * blockDim.x + threadIdx.x;
    if (i >= E + n) return;
    int sh = g_shift;
    int s, d;
    if (i < E) { s = ei32[(size_t)i << sh]; d = ei32[(size_t)(E + i) << sh]; }
    else       { s = d = i - E; }
    if (d < 0 || d >= n) return;
    int pos = g_offs[d] + atomicAdd(&g_cur[d], 1);
    g_src[pos] = s;
}

// ---------------- per-edge GATv2 attention scores (warp per edge) -------------
// edge p (CSR order): dst is implied by segment; recover via searching not needed:
// we read dst from a second pass over offsets instead — simpler: store dst too.
__device__ int g_dstArr[ETOT];

__global__ void scatter_dst_fill_k(int n) {
    // fill g_dstArr by segment: one warp per node writes its range
    int w = (blockIdx.x * blockDim.x + threadIdx.x) >> 5;
    int lane = threadIdx.x & 31;
    if (w >= n) return;
    int beg = g_offs[w], end = g_offs[w + 1];
    for (int p = beg + lane; p < end; p += 32) g_dstArr[p] = w;
}

__global__ void score_k(const float* __restrict__ att, int etot) {
    int w = (blockIdx.x * blockDim.x + threadIdx.x) >> 5;
    int lane = threadIdx.x & 31;
    if (w >= etot) return;
    int s = g_src[w];
    int d = g_dstArr[w];
    const float* xl = g_xl + (size_t)s * CH + lane;
    const float* xr = g_xr + (size_t)d * CH + lane;
    float sc[4];
    #pragma unroll
    for (int j = 0; j < 4; j++) {
        float v = xl[j * 32] + xr[j * 32];
        v = v > 0.f ? v : NEG_SLOPE * v;
        sc[j] = v * att[j * 32 + lane];
    }
    #pragma unroll
    for (int j = 0; j < 4; j++) {
        #pragma unroll
        for (int o = 16; o; o >>= 1) sc[j] += __shfl_xor_sync(0xFFFFFFFFu, sc[j], o);
    }
    if (lane == 0)
        g_score[w] = make_float4(sc[0], sc[1], sc[2], sc[3]);
}

// ---------------- warp-per-dst segment softmax + aggregation ------------------
__global__ void agg_k(const float* __restrict__ bias, int n) {
    int w = (blockIdx.x * blockDim.x + threadIdx.x) >> 5;
    int lane = threadIdx.x & 31;
    if (w >= n) return;
    int beg = g_offs[w], end = g_offs[w + 1];

    float m0 = -1e30f, m1 = -1e30f, m2 = -1e30f, m3 = -1e30f;
    for (int p = beg + lane; p < end; p += 32) {
        float4 sc = g_score[p];
        m0 = fmaxf(m0, sc.x); m1 = fmaxf(m1, sc.y);
        m2 = fmaxf(m2, sc.z); m3 = fmaxf(m3, sc.w);
    }
    #pragma unroll
    for (int o = 16; o; o >>= 1) {
        m0 = fmaxf(m0, __shfl_xor_sync(0xFFFFFFFFu, m0, o));
        m1 = fmaxf(m1, __shfl_xor_sync(0xFFFFFFFFu, m1, o));
        m2 = fmaxf(m2, __shfl_xor_sync(0xFFFFFFFFu, m2, o));
        m3 = fmaxf(m3, __shfl_xor_sync(0xFFFFFFFFu, m3, o));
    }

    float a0 = 0.f, a1 = 0.f, a2 = 0.f, a3 = 0.f;
    float d0 = 0.f, d1 = 0.f, d2 = 0.f, d3 = 0.f;
    for (int p = beg; p < end; ++p) {
        int s = g_src[p];
        float4 sc = g_score[p];
        float w0 = __expf(sc.x - m0);
        float w1 = __expf(sc.y - m1);
        float w2 = __expf(sc.z - m2);
        float w3 = __expf(sc.w - m3);
        d0 += w0; d1 += w1; d2 += w2; d3 += w3;
        const float* xp = g_xl + (size_t)s * CH + lane;
        a0 = fmaf(w0, xp[0],  a0);
        a1 = fmaf(w1, xp[32], a1);
        a2 = fmaf(w2, xp[64], a2);
        a3 = fmaf(w3, xp[96], a3);
    }
    float* op = g_pre + (size_t)w * CH + lane;
    op[0]  = a0 / d0 + bias[lane];
    op[32] = a1 / d1 + bias[lane + 32];
    op[64] = a2 / d2 + bias[lane + 64];
    op[96] = a3 / d3 + bias[lane + 96];
}

// ---------------- BN stats: per-channel sum & sumsq ---------------------------
__global__ void stats_k(int n) {
    __shared__ float ss[256], qq[256];
    int t = threadIdx.x;
    int c = t & 127;
    int half = t >> 7;
    float s = 0.f, q = 0.f;
    for (int r = blockIdx.x * 2 + half; r < n; r += gridDim.x * 2) {
        float v = g_pre[(size_t)r * CH + c];
        s += v;
        q = fmaf(v, v, q);
    }
    ss[t] = s; qq[t] = q;
    __syncthreads();
    if (t < 128) {
        s = ss[t] + ss[t + 128];
        q = qq[t] + qq[t + 128];
        atomicAdd(&g_sum[c], s);
        atomicAdd(&g_sumsq[c], q);
    }
}

// ---------------- final: BN + residual + ELU ----------------------------------
__global__ void final_k(const float* __restrict__ x,
                        const float* __restrict__ gamma,
                        const float* __restrict__ beta,
                        float* __restrict__ out, int n) {
    int idx = blockIdx.x * blockDim.x + threadIdx.x;
    if (idx >= n * CH) return;
    int c = idx & 127;
    float invn = 1.f / (float)n;
    float mu = g_sum[c] * invn;
    float var = g_sumsq[c] * invn - mu * mu;
    float y = (g_pre[idx] - mu) * rsqrtf(var + BN_EPS) * gamma[c] + beta[c] + x[idx];
    out[idx] = (y > 0.f) ? y : (__expf(y) - 1.f);
}

// ---------------- launch --------------------------------------------------------
extern "C" void kernel_launch(void* const* d_in, const int* in_sizes, int n_in,
                              void* d_out, int out_size) {
    const float* x     = (const float*)d_in[0];
    const int*   ei32  = (const int*)d_in[1];
    const float* Wl    = (const float*)d_in[2];
    const float* bl    = (const float*)d_in[3];
    const float* Wr    = (const float*)d_in[4];
    const float* br    = (const float*)d_in[5];
    const float* att   = (const float*)d_in[6];
    const float* bias  = (const float*)d_in[7];
    const float* gamma = (const float*)d_in[8];
    const float* beta  = (const float*)d_in[9];
    float*       out   = (float*)d_out;

    int n = in_sizes[0] / CH;          // 50000
    int E = in_sizes[1] / 2;           // 800000 (element count of (2,E) index array)
    int etot = E + n;

    const int T = 256;
    detect_k<<<1, 1024>>>(ei32);
    init_k<<<(n + T - 1) / T, T>>>();
    gemm_k<<<(n + 31) / 32, T>>>(x, Wl, bl, Wr, br, n);
    hist_k<<<(E + n + T - 1) / T, T>>>(ei32, E, n);
    scan_k<<<1, 1024>>>(n);
    scatter_k<<<(E + n + T - 1) / T, T>>>(ei32, E, n);
    scatter_dst_fill_k<<<(n * 32 + T - 1) / T, T>>>(n);
    score_k<<<((size_t)etot * 32 + T - 1) / T, T>>>(att, etot);
    agg_k<<<(n * 32 + T - 1) / T, T>>>(bias, n);
    stats_k<<<512, 256>>>(n);
    final_k<<<(n * CH + T - 1) / T, T>>>(x, gamma, beta, out, n);
}

// round 3
// speedup vs baseline: 1.8628x; 1.8628x over previous
#include <cuda_runtime.h>
#include <cuda_bf16.h>
#include <math.h>

#define N_NODES 50000
#define E_EDGES 800000
#define ETOT (E_EDGES + N_NODES)
#define CH 128
#define NEG_SLOPE 0.2f
#define BN_EPS 1e-5f
#define SCAN_B ((N_NODES + 255) / 256)   // 196

// ---------------- scratch (static device globals; no allocations) -------------
__device__ __align__(16) float g_xl[(size_t)N_NODES * CH];
__device__ __align__(16) float g_xr[(size_t)N_NODES * CH];
__device__ __align__(16) float g_pre[(size_t)N_NODES * CH];
__device__ int   g_deg[N_NODES];
__device__ int   g_cur[N_NODES];
__device__ int   g_offs[N_NODES + 1];
__device__ int   g_src[ETOT];
__device__ int   g_part[256];
__device__ float g_sum[CH];
__device__ float g_sumsq[CH];
__device__ int   g_shift;   // 0: edge_index int32; 1: int64 (read low word)

// ---------------- detect edge_index dtype --------------------------------------
__global__ void detect_k(const int* __restrict__ ei32) {
    __shared__ int any_nz;
    if (threadIdx.x == 0) any_nz = 0;
    __syncthreads();
    if (ei32[2 * threadIdx.x + 1] != 0) atomicOr(&any_nz, 1);
    __syncthreads();
    if (threadIdx.x == 0) g_shift = any_nz ? 0 : 1;
}

// ---------------- init ----------------------------------------------------------
__global__ void init_k() {
    int i = blockIdx.x * blockDim.x + threadIdx.x;
    if (i < N_NODES) { g_deg[i] = 0; g_cur[i] = 0; }
    if (i < CH) { g_sum[i] = 0.f; g_sumsq[i] = 0.f; }
}

// ---------------- register-tiled fused GEMM ------------------------------------
// block: 256 thr, tile 64 nodes x 256 cols (128 xl + 128 xr). thread: 8 nodes x
// (4 xl cols + 4 xr cols). W staged in smem; x tile transposed in smem.
__global__ void gemm_k(const float* __restrict__ x,
                       const float* __restrict__ Wl, const float* __restrict__ bl,
                       const float* __restrict__ Wr, const float* __restrict__ br,
                       int n) {
    __shared__ float xs[16][65];
    __shared__ float ws[16][256];
    int t  = threadIdx.x;
    int tc = t & 31;          // col group: xl cols tc*4.., xr cols tc*4..
    int tr = t >> 5;          // node group: nodes tr*8..tr*8+7
    int node0 = blockIdx.x * 64;

    float4 accl[8], accr[8];
    float4 bl4 = *(const float4*)&bl[tc * 4];
    float4 br4 = *(const float4*)&br[tc * 4];
    #pragma unroll
    for (int i = 0; i < 8; i++) { accl[i] = bl4; accr[i] = br4; }

    int ndl = t >> 2;          // 0..63 (load role)
    int q   = t & 3;

    for (int kc0 = 0; kc0 < CH; kc0 += 16) {
        // stage x tile (transposed)
        float4 v = make_float4(0.f, 0.f, 0.f, 0.f);
        if (node0 + ndl < n)
            v = *(const float4*)&x[(size_t)(node0 + ndl) * CH + kc0 + q * 4];
        xs[q * 4 + 0][ndl] = v.x;
        xs[q * 4 + 1][ndl] = v.y;
        xs[q * 4 + 2][ndl] = v.z;
        xs[q * 4 + 3][ndl] = v.w;
        // stage W tile: cols 0..127 from Wl, 128..255 from Wr
        #pragma unroll
        for (int r = 0; r < 4; r++) {
            int l = t + 256 * r;
            int k = l >> 6;
            int c = (l & 63) * 4;
            const float* Wsrc = (c < CH) ? (Wl + (size_t)(kc0 + k) * CH + c)
                                         : (Wr + (size_t)(kc0 + k) * CH + (c - CH));
            *(float4*)&ws[k][c] = *(const float4*)Wsrc;
        }
        __syncthreads();
        #pragma unroll
        for (int k = 0; k < 16; k++) {
            float a[8];
            #pragma unroll
            for (int i = 0; i < 8; i++) a[i] = xs[k][tr * 8 + i];
            float4 b0 = *(float4*)&ws[k][tc * 4];
            float4 b1 = *(float4*)&ws[k][128 + tc * 4];
            #pragma unroll
            for (int i = 0; i < 8; i++) {
                accl[i].x = fmaf(a[i], b0.x, accl[i].x);
                accl[i].y = fmaf(a[i], b0.y, accl[i].y);
                accl[i].z = fmaf(a[i], b0.z, accl[i].z);
                accl[i].w = fmaf(a[i], b0.w, accl[i].w);
                accr[i].x = fmaf(a[i], b1.x, accr[i].x);
                accr[i].y = fmaf(a[i], b1.y, accr[i].y);
                accr[i].z = fmaf(a[i], b1.z, accr[i].z);
                accr[i].w = fmaf(a[i], b1.w, accr[i].w);
            }
        }
        __syncthreads();
    }
    #pragma unroll
    for (int i = 0; i < 8; i++) {
        int node = node0 + tr * 8 + i;
        if (node < n) {
            *(float4*)&g_xl[(size_t)node * CH + tc * 4] = accl[i];
            *(float4*)&g_xr[(size_t)node * CH + tc * 4] = accr[i];
        }
    }
}

// ---------------- degree histogram ----------------------------------------------
__global__ void hist_k(const int* __restrict__ ei32, int E, int n) {
    int i = blockIdx.x * blockDim.x + threadIdx.x;
    if (i >= E + n) return;
    int sh = g_shift;
    int d = (i < E) ? ei32[(size_t)(E + i) << sh] : (i - E);
    if (d >= 0 && d < n) atomicAdd(&g_deg[d], 1);
}

// ---------------- 3-phase exclusive scan ----------------------------------------
__global__ void scan_a(int n) {
    __shared__ int s[256];
    int b = blockIdx.x, t = threadIdx.x, i = b * 256 + t;
    s[t] = (i < n) ? g_deg[i] : 0;
    __syncthreads();
    #pragma unroll
    for (int d = 1; d < 256; d <<= 1) {
        int v = (t >= d) ? s[t - d] : 0;
        __syncthreads();
        s[t] += v;
        __syncthreads();
    }
    if (i < n) g_offs[i] = s[t];          // inclusive, fixed up later
    if (t == 255) g_part[b] = s[255];
}
__global__ void scan_b(int nb) {
    __shared__ int s[256];
    int t = threadIdx.x;
    s[t] = (t < nb) ? g_part[t] : 0;
    __syncthreads();
    #pragma unroll
    for (int d = 1; d < 256; d <<= 1) {
        int v = (t >= d) ? s[t - d] : 0;
        __syncthreads();
        s[t] += v;
        __syncthreads();
    }
    g_part[t] = (t > 0) ? s[t - 1] : 0;   // exclusive block prefix
}
__global__ void scan_c(int n) {
    int b = blockIdx.x, t = threadIdx.x, i = b * 256 + t;
    if (i >= n) return;
    int incl = g_offs[i] + g_part[b];
    g_offs[i] = incl - g_deg[i];
    if (i == n - 1) g_offs[n] = incl;
}

// ---------------- scatter edges into CSR-by-dst order ---------------------------
__global__ void scatter_k(const int* __restrict__ ei32, int E, int n) {
    int i = blockIdx.x * blockDim.x + threadIdx.x;
    if (i >= E + n) return;
    int sh = g_shift;
    int s, d;
    if (i < E) { s = ei32[(size_t)i << sh]; d = ei32[(size_t)(E + i) << sh]; }
    else       { s = d = i - E; }
    if (d < 0 || d >= n) return;
    int pos = g_offs[d] + atomicAdd(&g_cur[d], 1);
    g_src[pos] = s;
}

// ---------------- fused softmax-attention aggregation ---------------------------
// warp per dst node. lane owns channels [4*lane, 4*lane+4) -> head = lane>>3.
// no max subtraction (scores are tiny); single gather pass over x_l[src].
__global__ void agg_k(const float* __restrict__ att,
                      const float* __restrict__ bias, int n) {
    int w = (blockIdx.x * blockDim.x + threadIdx.x) >> 5;
    int lane = threadIdx.x & 31;
    if (w >= n) return;
    int beg = g_offs[w], end = g_offs[w + 1];

    float4 r  = *(const float4*)&g_xr[(size_t)w * CH + lane * 4];
    float4 av = *(const float4*)&att[lane * 4];

    float a0 = 0.f, a1 = 0.f, a2 = 0.f, a3 = 0.f, den = 0.f;
    for (int p = beg; p < end; ++p) {
        int s = g_src[p];
        float4 xl = *(const float4*)&g_xl[(size_t)s * CH + lane * 4];
        float v0 = xl.x + r.x; v0 = v0 > 0.f ? v0 : NEG_SLOPE * v0;
        float v1 = xl.y + r.y; v1 = v1 > 0.f ? v1 : NEG_SLOPE * v1;
        float v2 = xl.z + r.z; v2 = v2 > 0.f ? v2 : NEG_SLOPE * v2;
        float v3 = xl.w + r.w; v3 = v3 > 0.f ? v3 : NEG_SLOPE * v3;
        float sc = fmaf(v0, av.x, fmaf(v1, av.y, fmaf(v2, av.z, v3 * av.w)));
        // sum within 8-lane head group
        sc += __shfl_xor_sync(0xFFFFFFFFu, sc, 1);
        sc += __shfl_xor_sync(0xFFFFFFFFu, sc, 2);
        sc += __shfl_xor_sync(0xFFFFFFFFu, sc, 4);
        float e = __expf(sc);
        den += e;
        a0 = fmaf(e, xl.x, a0);
        a1 = fmaf(e, xl.y, a1);
        a2 = fmaf(e, xl.z, a2);
        a3 = fmaf(e, xl.w, a3);
    }
    float inv = 1.f / den;
    float4 b4 = *(const float4*)&bias[lane * 4];
    float4 o;
    o.x = fmaf(a0, inv, b4.x);
    o.y = fmaf(a1, inv, b4.y);
    o.z = fmaf(a2, inv, b4.z);
    o.w = fmaf(a3, inv, b4.w);
    *(float4*)&g_pre[(size_t)w * CH + lane * 4] = o;
}

// ---------------- BN stats -------------------------------------------------------
__global__ void stats_k(int n) {
    __shared__ float ss[256], qq[256];
    int t = threadIdx.x;
    int c = t & 127;
    int half = t >> 7;
    float s = 0.f, q = 0.f;
    for (int r = blockIdx.x * 2 + half; r < n; r += gridDim.x * 2) {
        float v = g_pre[(size_t)r * CH + c];
        s += v;
        q = fmaf(v, v, q);
    }
    ss[t] = s; qq[t] = q;
    __syncthreads();
    if (t < 128) {
        s = ss[t] + ss[t + 128];
        q = qq[t] + qq[t + 128];
        atomicAdd(&g_sum[c], s);
        atomicAdd(&g_sumsq[c], q);
    }
}

// ---------------- final: BN + residual + ELU -------------------------------------
__global__ void final_k(const float* __restrict__ x,
                        const float* __restrict__ gamma,
                        const float* __restrict__ beta,
                        float* __restrict__ out, int n) {
    int idx = blockIdx.x * blockDim.x + threadIdx.x;
    if (idx >= n * CH) return;
    int c = idx & 127;
    float invn = 1.f / (float)n;
    float mu = g_sum[c] * invn;
    float var = g_sumsq[c] * invn - mu * mu;
    float y = (g_pre[idx] - mu) * rsqrtf(var + BN_EPS) * gamma[c] + beta[c] + x[idx];
    out[idx] = (y > 0.f) ? y : (__expf(y) - 1.f);
}

// ---------------- launch ----------------------------------------------------------
extern "C" void kernel_launch(void* const* d_in, const int* in_sizes, int n_in,
                              void* d_out, int out_size) {
    const float* x     = (const float*)d_in[0];
    const int*   ei32  = (const int*)d_in[1];
    const float* Wl    = (const float*)d_in[2];
    const float* bl    = (const float*)d_in[3];
    const float* Wr    = (const float*)d_in[4];
    const float* br    = (const float*)d_in[5];
    const float* att   = (const float*)d_in[6];
    const float* bias  = (const float*)d_in[7];
    const float* gamma = (const float*)d_in[8];
    const float* beta  = (const float*)d_in[9];
    float*       out   = (float*)d_out;

    int n = in_sizes[0] / CH;          // 50000
    int E = in_sizes[1] / 2;           // 800000
    int nb = (n + 255) / 256;

    const int T = 256;
    detect_k<<<1, 1024>>>(ei32);
    init_k<<<(n + T - 1) / T, T>>>();
    gemm_k<<<(n + 63) / 64, T>>>(x, Wl, bl, Wr, br, n);
    hist_k<<<(E + n + T - 1) / T, T>>>(ei32, E, n);
    scan_a<<<nb, 256>>>(n);
    scan_b<<<1, 256>>>(nb);
    scan_c<<<nb, 256>>>(n);
    scatter_k<<<(E + n + T - 1) / T, T>>>(ei32, E, n);
    agg_k<<<((size_t)n * 32 + T - 1) / T, T>>>(att, bias, n);
    stats_k<<<512, 256>>>(n);
    final_k<<<(n * CH + T - 1) / T, T>>>(x, gamma, beta, out, n);
}

// round 5
// speedup vs baseline: 2.3834x; 1.2794x over previous
#include <cuda_runtime.h>
#include <cuda_bf16.h>
#include <math.h>
#include <stdint.h>

#define N_NODES 50000
#define E_EDGES 800000
#define ETOT (E_EDGES + N_NODES)
#define CH 128
#define NEG_SLOPE 0.2f
#define BN_EPS 1e-5f
#define PADK 136   // bf16 per smem row (272B) -> conflict-free fragment reads

// ---------------- scratch (static device globals; no allocations) -------------
__device__ __align__(16) float g_xl[(size_t)N_NODES * CH];
__device__ __align__(16) float g_xr[(size_t)N_NODES * CH];
__device__ __align__(16) float g_pre[(size_t)N_NODES * CH];
__device__ __align__(16) __nv_bfloat16 g_xh[(size_t)N_NODES * CH];
__device__ __align__(16) __nv_bfloat16 g_xlo[(size_t)N_NODES * CH];
__device__ __align__(16) __nv_bfloat16 g_wh[256 * 128];    // [n=256][k=128]
__device__ __align__(16) __nv_bfloat16 g_wlo[256 * 128];
__device__ int   g_deg[N_NODES];
__device__ int   g_cur[N_NODES];
__device__ int   g_offs[N_NODES + 1];
__device__ int   g_src[ETOT];
__device__ int   g_part[256];
__device__ float g_sum[CH];
__device__ float g_sumsq[CH];
__device__ int   g_shift;   // 0: edge_index int32; 1: int64 (read low word)

// ---------------- init (+ dtype detect in block 0) ------------------------------
__global__ void init_k(const int* __restrict__ ei32) {
    int i = blockIdx.x * blockDim.x + threadIdx.x;
    if (i < N_NODES) { g_deg[i] = 0; g_cur[i] = 0; }
    if (i < CH) { g_sum[i] = 0.f; g_sumsq[i] = 0.f; }
    if (blockIdx.x == 0) {
        __shared__ int nz;
        if (threadIdx.x == 0) nz = 0;
        __syncthreads();
        if (ei32[2 * threadIdx.x + 1] != 0) atomicOr(&nz, 1);
        __syncthreads();
        if (threadIdx.x == 0) g_shift = nz ? 0 : 1;
    }
}

// ---------------- split x into bf16 hi/lo ---------------------------------------
__global__ void split_x_k(const float* __restrict__ x, int n4) {
    int i = blockIdx.x * blockDim.x + threadIdx.x;
    if (i >= n4) return;
    float4 v = ((const float4*)x)[i];
    __nv_bfloat16 h0 = __float2bfloat16(v.x), h1 = __float2bfloat16(v.y);
    __nv_bfloat16 h2 = __float2bfloat16(v.z), h3 = __float2bfloat16(v.w);
    __nv_bfloat16 l0 = __float2bfloat16(v.x - __bfloat162float(h0));
    __nv_bfloat16 l1 = __float2bfloat16(v.y - __bfloat162float(h1));
    __nv_bfloat16 l2 = __float2bfloat16(v.z - __bfloat162float(h2));
    __nv_bfloat16 l3 = __float2bfloat16(v.w - __bfloat162float(h3));
    ((__nv_bfloat162*)g_xh)[2 * i]      = __halves2bfloat162(h0, h1);
    ((__nv_bfloat162*)g_xh)[2 * i + 1]  = __halves2bfloat162(h2, h3);
    ((__nv_bfloat162*)g_xlo)[2 * i]     = __halves2bfloat162(l0, l1);
    ((__nv_bfloat162*)g_xlo)[2 * i + 1] = __halves2bfloat162(l2, l3);
}

// ---------------- transpose+split W into B layout [n=256][k=128] ----------------
__global__ void split_w_k(const float* __restrict__ Wl, const float* __restrict__ Wr) {
    int i = blockIdx.x * blockDim.x + threadIdx.x;   // i = nc*128 + k
    if (i >= 256 * 128) return;
    int nc = i >> 7, k = i & 127;
    float v = (nc < 128) ? Wl[k * 128 + nc] : Wr[k * 128 + (nc - 128)];
    __nv_bfloat16 h = __float2bfloat16(v);
    g_wh[i] = h;
    g_wlo[i] = __float2bfloat16(v - __bfloat162float(h));
}

// ---------------- HMMA m16n8k16 wrapper -----------------------------------------
__device__ __forceinline__ void mma16816(float* c, const uint32_t* a, const uint32_t* b) {
    asm volatile(
        "mma.sync.aligned.m16n8k16.row.col.f32.bf16.bf16.f32 "
        "{%0,%1,%2,%3}, {%4,%5,%6,%7}, {%8,%9}, {%0,%1,%2,%3};"
        : "+f"(c[0]), "+f"(c[1]), "+f"(c[2]), "+f"(c[3])
        : "r"(a[0]), "r"(a[1]), "r"(a[2]), "r"(a[3]), "r"(b[0]), "r"(b[1]));
}

// ---------------- tensor-core GEMM via mma.sync ----------------------------------
// grid (ceil(n/128), 2). by=0 -> W_l cols -> g_xl ; by=1 -> W_r cols -> g_xr.
// block 256 thr: warp grid 4 (row) x 2 (col); warp tile 32 rows x 64 cols.
// split precision: D = Ah*Bh + Ah*Bl + Al*Bh (fp32 accum).
__global__ void __launch_bounds__(256) gemm_mma_k(int n) {
    extern __shared__ __nv_bfloat16 sm[];
    __nv_bfloat16* sAh = sm;
    __nv_bfloat16* sAl = sAh + 128 * PADK;
    __nv_bfloat16* sBh = sAl + 128 * PADK;
    __nv_bfloat16* sBl = sBh + 128 * PADK;

    int t = threadIdx.x;
    int row0 = blockIdx.x * 128;
    int by = blockIdx.y;

    // stage tiles (uint4 = 8 bf16)
    for (int l = t; l < 2048; l += 256) {
        int r = l >> 4, j = l & 15;
        uint4 vh = make_uint4(0, 0, 0, 0), vl = make_uint4(0, 0, 0, 0);
        if (row0 + r < n) {
            vh = ((const uint4*)g_xh)[(size_t)(row0 + r) * 16 + j];
            vl = ((const uint4*)g_xlo)[(size_t)(row0 + r) * 16 + j];
        }
        *(uint4*)&sAh[r * PADK + j * 8] = vh;
        *(uint4*)&sAl[r * PADK + j * 8] = vl;
        uint4 wh = ((const uint4*)g_wh)[(size_t)(by * 128 + r) * 16 + j];
        uint4 wl = ((const uint4*)g_wlo)[(size_t)(by * 128 + r) * 16 + j];
        *(uint4*)&sBh[r * PADK + j * 8] = wh;
        *(uint4*)&sBl[r * PADK + j * 8] = wl;
    }
    __syncthreads();

    int warp = t >> 5, lane = t & 31;
    int rg = warp & 3, cg = warp >> 2;
    int lr = lane >> 2, lk = (lane & 3) * 2;

    float acc[2][8][4];
    #pragma unroll
    for (int mf = 0; mf < 2; mf++)
        #pragma unroll
        for (int nf = 0; nf < 8; nf++)
            #pragma unroll
            for (int q = 0; q < 4; q++) acc[mf][nf][q] = 0.f;

    #pragma unroll
    for (int ks = 0; ks < 8; ks++) {
        int k0 = ks * 16;
        uint32_t ah[2][4], al[2][4];
        #pragma unroll
        for (int mf = 0; mf < 2; mf++) {
            int rb = rg * 32 + mf * 16 + lr;
            ah[mf][0] = *(const uint32_t*)&sAh[(rb)     * PADK + k0 + lk];
            ah[mf][1] = *(const uint32_t*)&sAh[(rb + 8) * PADK + k0 + lk];
            ah[mf][2] = *(const uint32_t*)&sAh[(rb)     * PADK + k0 + 8 + lk];
            ah[mf][3] = *(const uint32_t*)&sAh[(rb + 8) * PADK + k0 + 8 + lk];
            al[mf][0] = *(const uint32_t*)&sAl[(rb)     * PADK + k0 + lk];
            al[mf][1] = *(const uint32_t*)&sAl[(rb + 8) * PADK + k0 + lk];
            al[mf][2] = *(const uint32_t*)&sAl[(rb)     * PADK + k0 + 8 + lk];
            al[mf][3] = *(const uint32_t*)&sAl[(rb + 8) * PADK + k0 + 8 + lk];
        }
        uint32_t bh[8][2], bl2[8][2];
        #pragma unroll
        for (int nf = 0; nf < 8; nf++) {
            int nb = cg * 64 + nf * 8 + lr;
            bh[nf][0]  = *(const uint32_t*)&sBh[nb * PADK + k0 + lk];
            bh[nf][1]  = *(const uint32_t*)&sBh[nb * PADK + k0 + 8 + lk];
            bl2[nf][0] = *(const uint32_t*)&sBl[nb * PADK + k0 + lk];
            bl2[nf][1] = *(const uint32_t*)&sBl[nb * PADK + k0 + 8 + lk];
        }
        #pragma unroll
        for (int mf = 0; mf < 2; mf++)
            #pragma unroll
            for (int nf = 0; nf < 8; nf++) {
                mma16816(acc[mf][nf], ah[mf], bh[nf]);
                mma16816(acc[mf][nf], ah[mf], bl2[nf]);
                mma16816(acc[mf][nf], al[mf], bh[nf]);
            }
    }

    float* dst = by ? g_xr : g_xl;
    #pragma unroll
    for (int mf = 0; mf < 2; mf++) {
        int row = row0 + rg * 32 + mf * 16 + lr;
        #pragma unroll
        for (int nf = 0; nf < 8; nf++) {
            int col = cg * 64 + nf * 8 + lk;
            if (row < n)
                *(float2*)&dst[(size_t)row * CH + col] =
                    make_float2(acc[mf][nf][0], acc[mf][nf][1]);
            if (row + 8 < n)
                *(float2*)&dst[(size_t)(row + 8) * CH + col] =
                    make_float2(acc[mf][nf][2], acc[mf][nf][3]);
        }
    }
}

// ---------------- degree histogram ----------------------------------------------
__global__ void hist_k(const int* __restrict__ ei32, int E, int n) {
    int i = blockIdx.x * blockDim.x + threadIdx.x;
    if (i >= E + n) return;
    int sh = g_shift;
    int d = (i < E) ? ei32[(size_t)(E + i) << sh] : (i - E);
    if (d >= 0 && d < n) atomicAdd(&g_deg[d], 1);
}

// ---------------- 3-phase exclusive scan ----------------------------------------
__global__ void scan_a(int n) {
    __shared__ int s[256];
    int b = blockIdx.x, t = threadIdx.x, i = b * 256 + t;
    s[t] = (i < n) ? g_deg[i] : 0;
    __syncthreads();
    #pragma unroll
    for (int d = 1; d < 256; d <<= 1) {
        int v = (t >= d) ? s[t - d] : 0;
        __syncthreads();
        s[t] += v;
        __syncthreads();
    }
    if (i < n) g_offs[i] = s[t];
    if (t == 255) g_part[b] = s[255];
}
__global__ void scan_b(int nb) {
    __shared__ int s[256];
    int t = threadIdx.x;
    s[t] = (t < nb) ? g_part[t] : 0;
    __syncthreads();
    #pragma unroll
    for (int d = 1; d < 256; d <<= 1) {
        int v = (t >= d) ? s[t - d] : 0;
        __syncthreads();
        s[t] += v;
        __syncthreads();
    }
    g_part[t] = (t > 0) ? s[t - 1] : 0;
}
__global__ void scan_c(int n) {
    int b = blockIdx.x, t = threadIdx.x, i = b * 256 + t;
    if (i >= n) return;
    int incl = g_offs[i] + g_part[b];
    g_offs[i] = incl - g_deg[i];
    if (i == n - 1) g_offs[n] = incl;
}

// ---------------- scatter edges into CSR-by-dst order ---------------------------
__global__ void scatter_k(const int* __restrict__ ei32, int E, int n) {
    int i = blockIdx.x * blockDim.x + threadIdx.x;
    if (i >= E + n) return;
    int sh = g_shift;
    int s, d;
    if (i < E) { s = ei32[(size_t)i << sh]; d = ei32[(size_t)(E + i) << sh]; }
    else       { s = d = i - E; }
    if (d < 0 || d >= n) return;
    int pos = g_offs[d] + atomicAdd(&g_cur[d], 1);
    g_src[pos] = s;
}

// ---------------- fused softmax-attention aggregation ---------------------------
// warp per dst node; lane owns channels [4*lane, 4*lane+4); head = lane>>3.
// GEMM outputs are bias-free: score uses r + (b_l+b_r); output adds b_l + bias.
__global__ void agg_k(const float* __restrict__ att, const float* __restrict__ bias,
                      const float* __restrict__ bl, const float* __restrict__ br, int n) {
    int w = (blockIdx.x * blockDim.x + threadIdx.x) >> 5;
    int lane = threadIdx.x & 31;
    if (w >= n) return;
    int beg = g_offs[w], end = g_offs[w + 1];

    float4 r   = *(const float4*)&g_xr[(size_t)w * CH + lane * 4];
    float4 blv = *(const float4*)&bl[lane * 4];
    float4 brv = *(const float4*)&br[lane * 4];
    float4 av  = *(const float4*)&att[lane * 4];
    float4 rs = make_float4(r.x + blv.x + brv.x, r.y + blv.y + brv.y,
                            r.z + blv.z + brv.z, r.w + blv.w + brv.w);

    float a0 = 0.f, a1 = 0.f, a2 = 0.f, a3 = 0.f, den = 0.f;

    int p = beg;
    for (; p + 2 <= end; p += 2) {
        int s0 = g_src[p], s1 = g_src[p + 1];
        float4 x0 = *(const float4*)&g_xl[(size_t)s0 * CH + lane * 4];
        float4 x1 = *(const float4*)&g_xl[(size_t)s1 * CH + lane * 4];
        {
            float v0 = x0.x + rs.x; v0 = v0 > 0.f ? v0 : NEG_SLOPE * v0;
            float v1 = x0.y + rs.y; v1 = v1 > 0.f ? v1 : NEG_SLOPE * v1;
            float v2 = x0.z + rs.z; v2 = v2 > 0.f ? v2 : NEG_SLOPE * v2;
            float v3 = x0.w + rs.w; v3 = v3 > 0.f ? v3 : NEG_SLOPE * v3;
            float sc = fmaf(v0, av.x, fmaf(v1, av.y, fmaf(v2, av.z, v3 * av.w)));
            sc += __shfl_xor_sync(0xFFFFFFFFu, sc, 1);
            sc += __shfl_xor_sync(0xFFFFFFFFu, sc, 2);
            sc += __shfl_xor_sync(0xFFFFFFFFu, sc, 4);
            float e = __expf(sc);
            den += e;
            a0 = fmaf(e, x0.x, a0); a1 = fmaf(e, x0.y, a1);
            a2 = fmaf(e, x0.z, a2); a3 = fmaf(e, x0.w, a3);
        }
        {
            float v0 = x1.x + rs.x; v0 = v0 > 0.f ? v0 : NEG_SLOPE * v0;
            float v1 = x1.y + rs.y; v1 = v1 > 0.f ? v1 : NEG_SLOPE * v1;
            float v2 = x1.z + rs.z; v2 = v2 > 0.f ? v2 : NEG_SLOPE * v2;
            float v3 = x1.w + rs.w; v3 = v3 > 0.f ? v3 : NEG_SLOPE * v3;
            float sc = fmaf(v0, av.x, fmaf(v1, av.y, fmaf(v2, av.z, v3 * av.w)));
            sc += __shfl_xor_sync(0xFFFFFFFFu, sc, 1);
            sc += __shfl_xor_sync(0xFFFFFFFFu, sc, 2);
            sc += __shfl_xor_sync(0xFFFFFFFFu, sc, 4);
            float e = __expf(sc);
            den += e;
            a0 = fmaf(e, x1.x, a0); a1 = fmaf(e, x1.y, a1);
            a2 = fmaf(e, x1.z, a2); a3 = fmaf(e, x1.w, a3);
        }
    }
    if (p < end) {
        int s0 = g_src[p];
        float4 x0 = *(const float4*)&g_xl[(size_t)s0 * CH + lane * 4];
        float v0 = x0.x + rs.x; v0 = v0 > 0.f ? v0 : NEG_SLOPE * v0;
        float v1 = x0.y + rs.y; v1 = v1 > 0.f ? v1 : NEG_SLOPE * v1;
        float v2 = x0.z + rs.z; v2 = v2 > 0.f ? v2 : NEG_SLOPE * v2;
        float v3 = x0.w + rs.w; v3 = v3 > 0.f ? v3 : NEG_SLOPE * v3;
        float sc = fmaf(v0, av.x, fmaf(v1, av.y, fmaf(v2, av.z, v3 * av.w)));
        sc += __shfl_xor_sync(0xFFFFFFFFu, sc, 1);
        sc += __shfl_xor_sync(0xFFFFFFFFu, sc, 2);
        sc += __shfl_xor_sync(0xFFFFFFFFu, sc, 4);
        float e = __expf(sc);
        den += e;
        a0 = fmaf(e, x0.x, a0); a1 = fmaf(e, x0.y, a1);
        a2 = fmaf(e, x0.z, a2); a3 = fmaf(e, x0.w, a3);
    }

    float inv = 1.f / den;
    float4 b4 = *(const float4*)&bias[lane * 4];
    float4 o;
    o.x = fmaf(a0, inv, b4.x + blv.x);
    o.y = fmaf(a1, inv, b4.y + blv.y);
    o.z = fmaf(a2, inv, b4.z + blv.z);
    o.w = fmaf(a3, inv, b4.w + blv.w);
    *(float4*)&g_pre[(size_t)w * CH + lane * 4] = o;
}

// ---------------- BN stats -------------------------------------------------------
__global__ void stats_k(int n) {
    __shared__ float ss[256], qq[256];
    int t = threadIdx.x;
    int c = t & 127;
    int half = t >> 7;
    float s = 0.f, q = 0.f;
    for (int r = blockIdx.x * 2 + half; r < n; r += gridDim.x * 2) {
        float v = g_pre[(size_t)r * CH + c];
        s += v;
        q = fmaf(v, v, q);
    }
    ss[t] = s; qq[t] = q;
    __syncthreads();
    if (t < 128) {
        s = ss[t] + ss[t + 128];
        q = qq[t] + qq[t + 128];
        atomicAdd(&g_sum[c], s);
        atomicAdd(&g_sumsq[c], q);
    }
}

// ---------------- final: BN + residual + ELU -------------------------------------
__global__ void final_k(const float* __restrict__ x,
                        const float* __restrict__ gamma,
                        const float* __restrict__ beta,
                        float* __restrict__ out, int n) {
    int idx = blockIdx.x * blockDim.x + threadIdx.x;
    if (idx >= n * CH) return;
    int c = idx & 127;
    float invn = 1.f / (float)n;
    float mu = g_sum[c] * invn;
    float var = g_sumsq[c] * invn - mu * mu;
    float y = (g_pre[idx] - mu) * rsqrtf(var + BN_EPS) * gamma[c] + beta[c] + x[idx];
    out[idx] = (y > 0.f) ? y : (__expf(y) - 1.f);
}

// ---------------- launch ----------------------------------------------------------
extern "C" void kernel_launch(void* const* d_in, const int* in_sizes, int n_in,
                              void* d_out, int out_size) {
    const float* x     = (const float*)d_in[0];
    const int*   ei32  = (const int*)d_in[1];
    const float* Wl    = (const float*)d_in[2];
    const float* bl    = (const float*)d_in[3];
    const float* Wr    = (const float*)d_in[4];
    const float* br    = (const float*)d_in[5];
    const float* att   = (const float*)d_in[6];
    const float* bias  = (const float*)d_in[7];
    const float* gamma = (const float*)d_in[8];
    const float* beta  = (const float*)d_in[9];
    float*       out   = (float*)d_out;

    int n = in_sizes[0] / CH;          // 50000
    int E = in_sizes[1] / 2;           // 800000
    int nb = (n + 255) / 256;

    const int SMEM_GEMM = 4 * 128 * PADK * (int)sizeof(__nv_bfloat16);  // 139264
    cudaFuncSetAttribute(gemm_mma_k, cudaFuncAttributeMaxDynamicSharedMemorySize, SMEM_GEMM);

    const int T = 256;
    init_k<<<nb, 256>>>(ei32);
    split_x_k<<<(n * 32 + T - 1) / T, T>>>(x, n * 32);
    split_w_k<<<128, 256>>>(Wl, Wr);
    dim3 gg((n + 127) / 128, 2);
    gemm_mma_k<<<gg, 256, SMEM_GEMM>>>(n);
    hist_k<<<(E + n + T - 1) / T, T>>>(ei32, E, n);
    scan_a<<<nb, 256>>>(n);
    scan_b<<<1, 256>>>(nb);
    scan_c<<<nb, 256>>>(n);
    scatter_k<<<(E + n + T - 1) / T, T>>>(ei32, E, n);
    agg_k<<<((size_t)n * 32 + T - 1) / T, T>>>(att, bias, bl, br, n);
    stats_k<<<512, 256>>>(n);
    final_k<<<(n * CH + T - 1) / T, T>>>(x, gamma, beta, out, n);
}

// round 7
// speedup vs baseline: 2.4702x; 1.0364x over previous
#include <cuda_runtime.h>
#include <cuda_bf16.h>
#include <math.h>
#include <stdint.h>

#define N_NODES 50000
#define E_EDGES 800000
#define ETOT (E_EDGES + N_NODES)
#define CH 128
#define NEG_SLOPE 0.2f
#define BN_EPS 1e-5f
#define PADK 136   // bf16 per smem row (272B) -> conflict-free ldmatrix phases

// ---------------- scratch (static device globals; no allocations) -------------
__device__ __align__(16) float g_xl[(size_t)N_NODES * CH];
__device__ __align__(16) float g_xr[(size_t)N_NODES * CH];
__device__ __align__(16) float g_pre[(size_t)N_NODES * CH];
__device__ __align__(16) __nv_bfloat16 g_wh[256 * 128];    // [n=256][k=128]
__device__ __align__(16) __nv_bfloat16 g_wlo[256 * 128];
__device__ int   g_deg[N_NODES];
__device__ int   g_cur[N_NODES];
__device__ int   g_offs[N_NODES + 1];
__device__ int   g_src[ETOT];
__device__ int   g_part[256];
__device__ float g_sum[CH];
__device__ float g_sumsq[CH];
__device__ int   g_shift;   // 0: edge_index int32; 1: int64 (read low word)

// ---------------- init (+ dtype detect in block 0) ------------------------------
__global__ void init_k(const int* __restrict__ ei32) {
    int i = blockIdx.x * blockDim.x + threadIdx.x;
    if (i < N_NODES) { g_deg[i] = 0; g_cur[i] = 0; }
    if (i < CH) { g_sum[i] = 0.f; g_sumsq[i] = 0.f; }
    if (blockIdx.x == 0) {
        __shared__ int nz;
        if (threadIdx.x == 0) nz = 0;
        __syncthreads();
        if (ei32[2 * threadIdx.x + 1] != 0) atomicOr(&nz, 1);
        __syncthreads();
        if (threadIdx.x == 0) g_shift = nz ? 0 : 1;
    }
}

// ---------------- transpose+split W into B layout [n=256][k=128] ----------------
__global__ void split_w_k(const float* __restrict__ Wl, const float* __restrict__ Wr) {
    int i = blockIdx.x * blockDim.x + threadIdx.x;   // i = nc*128 + k
    if (i >= 256 * 128) return;
    int nc = i >> 7, k = i & 127;
    float v = (nc < 128) ? Wl[k * 128 + nc] : Wr[k * 128 + (nc - 128)];
    __nv_bfloat16 h = __float2bfloat16(v);
    g_wh[i] = h;
    g_wlo[i] = __float2bfloat16(v - __bfloat162float(h));
}

// ---------------- mma / ldmatrix wrappers ----------------------------------------
__device__ __forceinline__ void mma16816(float* c, const uint32_t* a, const uint32_t* b) {
    asm volatile(
        "mma.sync.aligned.m16n8k16.row.col.f32.bf16.bf16.f32 "
        "{%0,%1,%2,%3}, {%4,%5,%6,%7}, {%8,%9}, {%0,%1,%2,%3};"
        : "+f"(c[0]), "+f"(c[1]), "+f"(c[2]), "+f"(c[3])
        : "r"(a[0]), "r"(a[1]), "r"(a[2]), "r"(a[3]), "r"(b[0]), "r"(b[1]));
}
__device__ __forceinline__ uint32_t smem_u32(const void* p) {
    uint32_t a;
    asm("{ .reg .u64 t; cvta.to.shared.u64 t, %1; cvt.u32.u64 %0, t; }" : "=r"(a) : "l"(p));
    return a;
}
#define LDMX4(r0, r1, r2, r3, a) \
    asm volatile("ldmatrix.sync.aligned.m8n8.x4.shared.b16 {%0,%1,%2,%3}, [%4];" \
        : "=r"(r0), "=r"(r1), "=r"(r2), "=r"(r3) : "r"(a))

// ---------------- tensor-core GEMM via mma.sync + ldmatrix -----------------------
// grid (ceil(n/64), 2). by=0 -> W_l -> g_xl ; by=1 -> W_r -> g_xr.
// block 256 thr: warp grid 2 (row) x 4 (col); warp tile 32 rows x 32 cols.
// A tile 64 rows staged from fp32 x with in-register hi/lo bf16 split.
// split precision: D = Ah*Bh + Ah*Bl + Al*Bh (fp32 accum).
__global__ void __launch_bounds__(256) gemm_mma_k(const float* __restrict__ x, int n) {
    extern __shared__ __nv_bfloat16 sm[];
    __nv_bfloat16* sAh = sm;                     //  64 x PADK
    __nv_bfloat16* sAl = sAh + 64 * PADK;        //  64 x PADK
    __nv_bfloat16* sBh = sAl + 64 * PADK;        // 128 x PADK
    __nv_bfloat16* sBl = sBh + 128 * PADK;       // 128 x PADK

    int t = threadIdx.x;
    int row0 = blockIdx.x * 64;
    int by = blockIdx.y;

    // stage A: read fp32 x, split hi/lo in registers (4 bf16 per store)
    // 64 rows x 32 float4 per row = 2048 loads
    for (int l = t; l < 2048; l += 256) {
        int r = l >> 5, j = l & 31;              // row r, float4 col j (k = 4j..4j+3)
        float4 v = make_float4(0.f, 0.f, 0.f, 0.f);
        if (row0 + r < n) v = ((const float4*)x)[(size_t)(row0 + r) * 32 + j];
        __nv_bfloat16 h0 = __float2bfloat16(v.x), h1 = __float2bfloat16(v.y);
        __nv_bfloat16 h2 = __float2bfloat16(v.z), h3 = __float2bfloat16(v.w);
        __nv_bfloat162 hA = __halves2bfloat162(h0, h1), hB = __halves2bfloat162(h2, h3);
        __nv_bfloat162 lA = __halves2bfloat162(__float2bfloat16(v.x - __bfloat162float(h0)),
                                               __float2bfloat16(v.y - __bfloat162float(h1)));
        __nv_bfloat162 lB = __halves2bfloat162(__float2bfloat16(v.z - __bfloat162float(h2)),
                                               __float2bfloat16(v.w - __bfloat162float(h3)));
        *(uint2*)&sAh[r * PADK + j * 4] = make_uint2(*(uint32_t*)&hA, *(uint32_t*)&hB);
        *(uint2*)&sAl[r * PADK + j * 4] = make_uint2(*(uint32_t*)&lA, *(uint32_t*)&lB);
    }
    // stage B from pre-split weights: 128 rows x 16 uint4 (8 bf16) per row
    for (int l = t; l < 2048; l += 256) {
        int r = l >> 4, j = l & 15;
        *(uint4*)&sBh[r * PADK + j * 8] = ((const uint4*)g_wh)[(size_t)(by * 128 + r) * 16 + j];
        *(uint4*)&sBl[r * PADK + j * 8] = ((const uint4*)g_wlo)[(size_t)(by * 128 + r) * 16 + j];
    }
    __syncthreads();

    int warp = t >> 5, lane = t & 31;
    int rg = warp >> 2, cg = warp & 3;           // 2 row-groups x 4 col-groups
    int lr = lane >> 2, lk = (lane & 3) * 2;

    // ldmatrix lane addresses (bytes, shared space)
    uint32_t aRow = (uint32_t)(rg * 32 + (lane & 15));
    uint32_t aKof = (uint32_t)((lane >> 4) << 3);
    uint32_t aOff = (aRow * PADK + aKof) * 2;
    uint32_t ah_base = smem_u32(sAh) + aOff;
    uint32_t al_base = smem_u32(sAl) + aOff;
    uint32_t bRow = (uint32_t)(cg * 32 + (lane & 7) + ((lane >> 4) << 3));
    uint32_t bKof = (uint32_t)(((lane >> 3) & 1) << 3);
    uint32_t bOff = (bRow * PADK + bKof) * 2;
    uint32_t bh_base = smem_u32(sBh) + bOff;
    uint32_t bl_base = smem_u32(sBl) + bOff;
    const uint32_t MF_STEP = 16 * PADK * 2;      // +16 rows

    float acc[2][4][4];
    #pragma unroll
    for (int mf = 0; mf < 2; mf++)
        #pragma unroll
        for (int nf = 0; nf < 4; nf++)
            #pragma unroll
            for (int q = 0; q < 4; q++) acc[mf][nf][q] = 0.f;

    #pragma unroll
    for (int ks = 0; ks < 8; ks++) {
        uint32_t ko = (uint32_t)ks * 32;         // 16 bf16 = 32 bytes
        uint32_t ah[2][4], al[2][4], bh[4][2], bl2[4][2];
        LDMX4(ah[0][0], ah[0][1], ah[0][2], ah[0][3], ah_base + ko);
        LDMX4(ah[1][0], ah[1][1], ah[1][2], ah[1][3], ah_base + MF_STEP + ko);
        LDMX4(al[0][0], al[0][1], al[0][2], al[0][3], al_base + ko);
        LDMX4(al[1][0], al[1][1], al[1][2], al[1][3], al_base + MF_STEP + ko);
        LDMX4(bh[0][0], bh[0][1], bh[1][0], bh[1][1], bh_base + ko);
        LDMX4(bh[2][0], bh[2][1], bh[3][0], bh[3][1], bh_base + MF_STEP + ko);
        LDMX4(bl2[0][0], bl2[0][1], bl2[1][0], bl2[1][1], bl_base + ko);
        LDMX4(bl2[2][0], bl2[2][1], bl2[3][0], bl2[3][1], bl_base + MF_STEP + ko);
        #pragma unroll
        for (int mf = 0; mf < 2; mf++)
            #pragma unroll
            for (int nf = 0; nf < 4; nf++) {
                mma16816(acc[mf][nf], ah[mf], bh[nf]);
                mma16816(acc[mf][nf], ah[mf], bl2[nf]);
                mma16816(acc[mf][nf], al[mf], bh[nf]);
            }
    }

    float* dst = by ? g_xr : g_xl;
    #pragma unroll
    for (int mf = 0; mf < 2; mf++) {
        int row = row0 + rg * 32 + mf * 16 + lr;
        #pragma unroll
        for (int nf = 0; nf < 4; nf++) {
            int col = cg * 32 + nf * 8 + lk;
            if (row < n)
                *(float2*)&dst[(size_t)row * CH + col] =
                    make_float2(acc[mf][nf][0], acc[mf][nf][1]);
            if (row + 8 < n)
                *(float2*)&dst[(size_t)(row + 8) * CH + col] =
                    make_float2(acc[mf][nf][2], acc[mf][nf][3]);
        }
    }
}

// ---------------- degree histogram ----------------------------------------------
__global__ void hist_k(const int* __restrict__ ei32, int E, int n) {
    int i = blockIdx.x * blockDim.x + threadIdx.x;
    if (i >= E + n) return;
    int sh = g_shift;
    int d = (i < E) ? ei32[(size_t)(E + i) << sh] : (i - E);
    if (d >= 0 && d < n) atomicAdd(&g_deg[d], 1);
}

// ---------------- 3-phase exclusive scan ----------------------------------------
__global__ void scan_a(int n) {
    __shared__ int s[256];
    int b = blockIdx.x, t = threadIdx.x, i = b * 256 + t;
    s[t] = (i < n) ? g_deg[i] : 0;
    __syncthreads();
    #pragma unroll
    for (int d = 1; d < 256; d <<= 1) {
        int v = (t >= d) ? s[t - d] : 0;
        __syncthreads();
        s[t] += v;
        __syncthreads();
    }
    if (i < n) g_offs[i] = s[t];
    if (t == 255) g_part[b] = s[255];
}
__global__ void scan_b(int nb) {
    __shared__ int s[256];
    int t = threadIdx.x;
    s[t] = (t < nb) ? g_part[t] : 0;
    __syncthreads();
    #pragma unroll
    for (int d = 1; d < 256; d <<= 1) {
        int v = (t >= d) ? s[t - d] : 0;
        __syncthreads();
        s[t] += v;
        __syncthreads();
    }
    g_part[t] = (t > 0) ? s[t - 1] : 0;
}
__global__ void scan_c(int n) {
    int b = blockIdx.x, t = threadIdx.x, i = b * 256 + t;
    if (i >= n) return;
    int incl = g_offs[i] + g_part[b];
    g_offs[i] = incl - g_deg[i];
    if (i == n - 1) g_offs[n] = incl;
}

// ---------------- scatter edges into CSR-by-dst order ---------------------------
__global__ void scatter_k(const int* __restrict__ ei32, int E, int n) {
    int i = blockIdx.x * blockDim.x + threadIdx.x;
    if (i >= E + n) return;
    int sh = g_shift;
    int s, d;
    if (i < E) { s = ei32[(size_t)i << sh]; d = ei32[(size_t)(E + i) << sh]; }
    else       { s = d = i - E; }
    if (d < 0 || d >= n) return;
    int pos = g_offs[d] + atomicAdd(&g_cur[d], 1);
    g_src[pos] = s;
}

// ---------------- fused softmax-attention aggregation ---------------------------
__global__ void agg_k(const float* __restrict__ att, const float* __restrict__ bias,
                      const float* __restrict__ bl, const float* __restrict__ br, int n) {
    int w = (blockIdx.x * blockDim.x + threadIdx.x) >> 5;
    int lane = threadIdx.x & 31;
    if (w >= n) return;
    int beg = g_offs[w], end = g_offs[w + 1];

    float4 r   = *(const float4*)&g_xr[(size_t)w * CH + lane * 4];
    float4 blv = *(const float4*)&bl[lane * 4];
    float4 brv = *(const float4*)&br[lane * 4];
    float4 av  = *(const float4*)&att[lane * 4];
    float4 rs = make_float4(r.x + blv.x + brv.x, r.y + blv.y + brv.y,
                            r.z + blv.z + brv.z, r.w + blv.w + brv.w);

    float a0 = 0.f, a1 = 0.f, a2 = 0.f, a3 = 0.f, den = 0.f;

    int p = beg;
    for (; p + 2 <= end; p += 2) {
        int s0 = g_src[p], s1 = g_src[p + 1];
        float4 x0 = *(const float4*)&g_xl[(size_t)s0 * CH + lane * 4];
        float4 x1 = *(const float4*)&g_xl[(size_t)s1 * CH + lane * 4];
        {
            float v0 = x0.x + rs.x; v0 = v0 > 0.f ? v0 : NEG_SLOPE * v0;
            float v1 = x0.y + rs.y; v1 = v1 > 0.f ? v1 : NEG_SLOPE * v1;
            float v2 = x0.z + rs.z; v2 = v2 > 0.f ? v2 : NEG_SLOPE * v2;
            float v3 = x0.w + rs.w; v3 = v3 > 0.f ? v3 : NEG_SLOPE * v3;
            float sc = fmaf(v0, av.x, fmaf(v1, av.y, fmaf(v2, av.z, v3 * av.w)));
            sc += __shfl_xor_sync(0xFFFFFFFFu, sc, 1);
            sc += __shfl_xor_sync(0xFFFFFFFFu, sc, 2);
            sc += __shfl_xor_sync(0xFFFFFFFFu, sc, 4);
            float e = __expf(sc);
            den += e;
            a0 = fmaf(e, x0.x, a0); a1 = fmaf(e, x0.y, a1);
            a2 = fmaf(e, x0.z, a2); a3 = fmaf(e, x0.w, a3);
        }
        {
            float v0 = x1.x + rs.x; v0 = v0 > 0.f ? v0 : NEG_SLOPE * v0;
            float v1 = x1.y + rs.y; v1 = v1 > 0.f ? v1 : NEG_SLOPE * v1;
            float v2 = x1.z + rs.z; v2 = v2 > 0.f ? v2 : NEG_SLOPE * v2;
            float v3 = x1.w + rs.w; v3 = v3 > 0.f ? v3 : NEG_SLOPE * v3;
            float sc = fmaf(v0, av.x, fmaf(v1, av.y, fmaf(v2, av.z, v3 * av.w)));
            sc += __shfl_xor_sync(0xFFFFFFFFu, sc, 1);
            sc += __shfl_xor_sync(0xFFFFFFFFu, sc, 2);
            sc += __shfl_xor_sync(0xFFFFFFFFu, sc, 4);
            float e = __expf(sc);
            den += e;
            a0 = fmaf(e, x1.x, a0); a1 = fmaf(e, x1.y, a1);
            a2 = fmaf(e, x1.z, a2); a3 = fmaf(e, x1.w, a3);
        }
    }
    if (p < end) {
        int s0 = g_src[p];
        float4 x0 = *(const float4*)&g_xl[(size_t)s0 * CH + lane * 4];
        float v0 = x0.x + rs.x; v0 = v0 > 0.f ? v0 : NEG_SLOPE * v0;
        float v1 = x0.y + rs.y; v1 = v1 > 0.f ? v1 : NEG_SLOPE * v1;
        float v2 = x0.z + rs.z; v2 = v2 > 0.f ? v2 : NEG_SLOPE * v2;
        float v3 = x0.w + rs.w; v3 = v3 > 0.f ? v3 : NEG_SLOPE * v3;
        float sc = fmaf(v0, av.x, fmaf(v1, av.y, fmaf(v2, av.z, v3 * av.w)));
        sc += __shfl_xor_sync(0xFFFFFFFFu, sc, 1);
        sc += __shfl_xor_sync(0xFFFFFFFFu, sc, 2);
        sc += __shfl_xor_sync(0xFFFFFFFFu, sc, 4);
        float e = __expf(sc);
        den += e;
        a0 = fmaf(e, x0.x, a0); a1 = fmaf(e, x0.y, a1);
        a2 = fmaf(e, x0.z, a2); a3 = fmaf(e, x0.w, a3);
    }

    float inv = 1.f / den;
    float4 b4 = *(const float4*)&bias[lane * 4];
    float4 o;
    o.x = fmaf(a0, inv, b4.x + blv.x);
    o.y = fmaf(a1, inv, b4.y + blv.y);
    o.z = fmaf(a2, inv, b4.z + blv.z);
    o.w = fmaf(a3, inv, b4.w + blv.w);
    *(float4*)&g_pre[(size_t)w * CH + lane * 4] = o;
}

// ---------------- BN stats -------------------------------------------------------
__global__ void stats_k(int n) {
    __shared__ float ss[256], qq[256];
    int t = threadIdx.x;
    int c = t & 127;
    int half = t >> 7;
    float s = 0.f, q = 0.f;
    for (int r = blockIdx.x * 2 + half; r < n; r += gridDim.x * 2) {
        float v = g_pre[(size_t)r * CH + c];
        s += v;
        q = fmaf(v, v, q);
    }
    ss[t] = s; qq[t] = q;
    __syncthreads();
    if (t < 128) {
        s = ss[t] + ss[t + 128];
        q = qq[t] + qq[t + 128];
        atomicAdd(&g_sum[c], s);
        atomicAdd(&g_sumsq[c], q);
    }
}

// ---------------- final: BN + residual + ELU -------------------------------------
__global__ void final_k(const float* __restrict__ x,
                        const float* __restrict__ gamma,
                        const float* __restrict__ beta,
                        float* __restrict__ out, int n) {
    int idx = blockIdx.x * blockDim.x + threadIdx.x;
    if (idx >= n * CH) return;
    int c = idx & 127;
    float invn = 1.f / (float)n;
    float mu = g_sum[c] * invn;
    float var = g_sumsq[c] * invn - mu * mu;
    float y = (g_pre[idx] - mu) * rsqrtf(var + BN_EPS) * gamma[c] + beta[c] + x[idx];
    out[idx] = (y > 0.f) ? y : (__expf(y) - 1.f);
}

// ---------------- launch ----------------------------------------------------------
extern "C" void kernel_launch(void* const* d_in, const int* in_sizes, int n_in,
                              void* d_out, int out_size) {
    const float* x     = (const float*)d_in[0];
    const int*   ei32  = (const int*)d_in[1];
    const float* Wl    = (const float*)d_in[2];
    const float* bl    = (const float*)d_in[3];
    const float* Wr    = (const float*)d_in[4];
    const float* br    = (const float*)d_in[5];
    const float* att   = (const float*)d_in[6];
    const float* bias  = (const float*)d_in[7];
    const float* gamma = (const float*)d_in[8];
    const float* beta  = (const float*)d_in[9];
    float*       out   = (float*)d_out;

    int n = in_sizes[0] / CH;          // 50000
    int E = in_sizes[1] / 2;           // 800000
    int nb = (n + 255) / 256;

    // smem: A(h+l) 2*64*PADK + B(h+l) 2*128*PADK bf16 = 104448 bytes
    const int SMEM_GEMM = (2 * 64 + 2 * 128) * PADK * (int)sizeof(__nv_bfloat16);
    cudaFuncSetAttribute(gemm_mma_k, cudaFuncAttributeMaxDynamicSharedMemorySize, SMEM_GEMM);

    const int T = 256;
    init_k<<<nb, 256>>>(ei32);
    split_w_k<<<128, 256>>>(Wl, Wr);
    dim3 gg((n + 63) / 64, 2);
    gemm_mma_k<<<gg, 256, SMEM_GEMM>>>(x, n);
    hist_k<<<(E + n + T - 1) / T, T>>>(ei32, E, n);
    scan_a<<<nb, 256>>>(n);
    scan_b<<<1, 256>>>(nb);
    scan_c<<<nb, 256>>>(n);
    scatter_k<<<(E + n + T - 1) / T, T>>>(ei32, E, n);
    agg_k<<<((size_t)n * 32 + T - 1) / T, T>>>(att, bias, bl, br, n);
    stats_k<<<512, 256>>>(n);
    final_k<<<(n * CH + T - 1) / T, T>>>(x, gamma, beta, out, n);
}

// round 8
// speedup vs baseline: 2.7465x; 1.1119x over previous
#include <cuda_runtime.h>
#include <cuda_bf16.h>
#include <math.h>
#include <stdint.h>

#define N_NODES 50000
#define E_EDGES 800000
#define ETOT (E_EDGES + N_NODES)
#define CH 128
#define NEG_SLOPE 0.2f
#define BN_EPS 1e-5f
#define PADK 136   // bf16 per smem row (272B) -> conflict-free ldmatrix phases

// ---------------- scratch (static device globals; no allocations) -------------
__device__ __align__(16) float g_xl[(size_t)N_NODES * CH];
__device__ __align__(16) float g_xr[(size_t)N_NODES * CH];
__device__ __align__(16) float g_pre[(size_t)N_NODES * CH];
__device__ __align__(16) __nv_bfloat16 g_wh[256 * 128];    // [n=256][k=128]
__device__ __align__(16) __nv_bfloat16 g_wlo[256 * 128];
__device__ int   g_deg[N_NODES];
__device__ int   g_cur[N_NODES];
__device__ int   g_offs[N_NODES + 1];
__device__ int   g_src[ETOT];
__device__ int   g_part[256];
__device__ float g_sum[CH];
__device__ float g_sumsq[CH];
__device__ int   g_shift;   // 0: edge_index int32; 1: int64 (read low word)

// ---------------- init (+ dtype detect in block 0) ------------------------------
__global__ void init_k(const int* __restrict__ ei32) {
    int i = blockIdx.x * blockDim.x + threadIdx.x;
    if (i < N_NODES) { g_deg[i] = 0; g_cur[i] = 0; }
    if (i < CH) { g_sum[i] = 0.f; g_sumsq[i] = 0.f; }
    if (blockIdx.x == 0) {
        __shared__ int nz;
        if (threadIdx.x == 0) nz = 0;
        __syncthreads();
        if (ei32[2 * threadIdx.x + 1] != 0) atomicOr(&nz, 1);
        __syncthreads();
        if (threadIdx.x == 0) g_shift = nz ? 0 : 1;
    }
}

// ---------------- transpose+split W into B layout [n=256][k=128] ----------------
__global__ void split_w_k(const float* __restrict__ Wl, const float* __restrict__ Wr) {
    int i = blockIdx.x * blockDim.x + threadIdx.x;   // i = nc*128 + k
    if (i >= 256 * 128) return;
    int nc = i >> 7, k = i & 127;
    float v = (nc < 128) ? Wl[k * 128 + nc] : Wr[k * 128 + (nc - 128)];
    __nv_bfloat16 h = __float2bfloat16(v);
    g_wh[i] = h;
    g_wlo[i] = __float2bfloat16(v - __bfloat162float(h));
}

// ---------------- mma / ldmatrix wrappers ----------------------------------------
__device__ __forceinline__ void mma16816(float* c, const uint32_t* a, const uint32_t* b) {
    asm volatile(
        "mma.sync.aligned.m16n8k16.row.col.f32.bf16.bf16.f32 "
        "{%0,%1,%2,%3}, {%4,%5,%6,%7}, {%8,%9}, {%0,%1,%2,%3};"
        : "+f"(c[0]), "+f"(c[1]), "+f"(c[2]), "+f"(c[3])
        : "r"(a[0]), "r"(a[1]), "r"(a[2]), "r"(a[3]), "r"(b[0]), "r"(b[1]));
}
__device__ __forceinline__ uint32_t smem_u32(const void* p) {
    uint32_t a;
    asm("{ .reg .u64 t; cvta.to.shared.u64 t, %1; cvt.u32.u64 %0, t; }" : "=r"(a) : "l"(p));
    return a;
}
#define LDMX4(r0, r1, r2, r3, a) \
    asm volatile("ldmatrix.sync.aligned.m8n8.x4.shared.b16 {%0,%1,%2,%3}, [%4];" \
        : "=r"(r0), "=r"(r1), "=r"(r2), "=r"(r3) : "r"(a))

// ---------------- tensor-core GEMM via mma.sync + ldmatrix -----------------------
// grid (ceil(n/64), 2). by=0 -> W_l -> g_xl ; by=1 -> W_r -> g_xr.
// block 256 thr: warp grid 2 (row) x 4 (col); warp tile 32 rows x 32 cols.
// split precision: D = Ah*Bh + Ah*Bl + Al*Bh (fp32 accum).
__global__ void __launch_bounds__(256) gemm_mma_k(const float* __restrict__ x, int n) {
    extern __shared__ __nv_bfloat16 sm[];
    __nv_bfloat16* sAh = sm;                     //  64 x PADK
    __nv_bfloat16* sAl = sAh + 64 * PADK;        //  64 x PADK
    __nv_bfloat16* sBh = sAl + 64 * PADK;        // 128 x PADK
    __nv_bfloat16* sBl = sBh + 128 * PADK;       // 128 x PADK

    int t = threadIdx.x;
    int row0 = blockIdx.x * 64;
    int by = blockIdx.y;

    // stage A: read fp32 x, split hi/lo in registers; 64 rows x 32 float4
    for (int l = t; l < 2048; l += 256) {
        int r = l >> 5, j = l & 31;
        float4 v = make_float4(0.f, 0.f, 0.f, 0.f);
        if (row0 + r < n) v = ((const float4*)x)[(size_t)(row0 + r) * 32 + j];
        __nv_bfloat16 h0 = __float2bfloat16(v.x), h1 = __float2bfloat16(v.y);
        __nv_bfloat16 h2 = __float2bfloat16(v.z), h3 = __float2bfloat16(v.w);
        __nv_bfloat162 hA = __halves2bfloat162(h0, h1), hB = __halves2bfloat162(h2, h3);
        __nv_bfloat162 lA = __halves2bfloat162(__float2bfloat16(v.x - __bfloat162float(h0)),
                                               __float2bfloat16(v.y - __bfloat162float(h1)));
        __nv_bfloat162 lB = __halves2bfloat162(__float2bfloat16(v.z - __bfloat162float(h2)),
                                               __float2bfloat16(v.w - __bfloat162float(h3)));
        *(uint2*)&sAh[r * PADK + j * 4] = make_uint2(*(uint32_t*)&hA, *(uint32_t*)&hB);
        *(uint2*)&sAl[r * PADK + j * 4] = make_uint2(*(uint32_t*)&lA, *(uint32_t*)&lB);
    }
    // stage B from pre-split weights: 128 rows x 16 uint4
    for (int l = t; l < 2048; l += 256) {
        int r = l >> 4, j = l & 15;
        *(uint4*)&sBh[r * PADK + j * 8] = ((const uint4*)g_wh)[(size_t)(by * 128 + r) * 16 + j];
        *(uint4*)&sBl[r * PADK + j * 8] = ((const uint4*)g_wlo)[(size_t)(by * 128 + r) * 16 + j];
    }
    __syncthreads();

    int warp = t >> 5, lane = t & 31;
    int rg = warp >> 2, cg = warp & 3;
    int lr = lane >> 2, lk = (lane & 3) * 2;

    uint32_t aRow = (uint32_t)(rg * 32 + (lane & 15));
    uint32_t aKof = (uint32_t)((lane >> 4) << 3);
    uint32_t aOff = (aRow * PADK + aKof) * 2;
    uint32_t ah_base = smem_u32(sAh) + aOff;
    uint32_t al_base = smem_u32(sAl) + aOff;
    uint32_t bRow = (uint32_t)(cg * 32 + (lane & 7) + ((lane >> 4) << 3));
    uint32_t bKof = (uint32_t)(((lane >> 3) & 1) << 3);
    uint32_t bOff = (bRow * PADK + bKof) * 2;
    uint32_t bh_base = smem_u32(sBh) + bOff;
    uint32_t bl_base = smem_u32(sBl) + bOff;
    const uint32_t MF_STEP = 16 * PADK * 2;

    float acc[2][4][4];
    #pragma unroll
    for (int mf = 0; mf < 2; mf++)
        #pragma unroll
        for (int nf = 0; nf < 4; nf++)
            #pragma unroll
            for (int q = 0; q < 4; q++) acc[mf][nf][q] = 0.f;

    #pragma unroll
    for (int ks = 0; ks < 8; ks++) {
        uint32_t ko = (uint32_t)ks * 32;
        uint32_t ah[2][4], al[2][4], bh[4][2], bl2[4][2];
        LDMX4(ah[0][0], ah[0][1], ah[0][2], ah[0][3], ah_base + ko);
        LDMX4(ah[1][0], ah[1][1], ah[1][2], ah[1][3], ah_base + MF_STEP + ko);
        LDMX4(al[0][0], al[0][1], al[0][2], al[0][3], al_base + ko);
        LDMX4(al[1][0], al[1][1], al[1][2], al[1][3], al_base + MF_STEP + ko);
        LDMX4(bh[0][0], bh[0][1], bh[1][0], bh[1][1], bh_base + ko);
        LDMX4(bh[2][0], bh[2][1], bh[3][0], bh[3][1], bh_base + MF_STEP + ko);
        LDMX4(bl2[0][0], bl2[0][1], bl2[1][0], bl2[1][1], bl_base + ko);
        LDMX4(bl2[2][0], bl2[2][1], bl2[3][0], bl2[3][1], bl_base + MF_STEP + ko);
        #pragma unroll
        for (int mf = 0; mf < 2; mf++)
            #pragma unroll
            for (int nf = 0; nf < 4; nf++) {
                mma16816(acc[mf][nf], ah[mf], bh[nf]);
                mma16816(acc[mf][nf], ah[mf], bl2[nf]);
                mma16816(acc[mf][nf], al[mf], bh[nf]);
            }
    }

    float* dst = by ? g_xr : g_xl;
    #pragma unroll
    for (int mf = 0; mf < 2; mf++) {
        int row = row0 + rg * 32 + mf * 16 + lr;
        #pragma unroll
        for (int nf = 0; nf < 4; nf++) {
            int col = cg * 32 + nf * 8 + lk;
            if (row < n)
                *(float2*)&dst[(size_t)row * CH + col] =
                    make_float2(acc[mf][nf][0], acc[mf][nf][1]);
            if (row + 8 < n)
                *(float2*)&dst[(size_t)(row + 8) * CH + col] =
                    make_float2(acc[mf][nf][2], acc[mf][nf][3]);
        }
    }
}

// ---------------- degree histogram (grid-stride) ---------------------------------
__global__ void hist_k(const int* __restrict__ ei32, int E, int n) {
    int sh = g_shift;
    int tot = E + n;
    for (int i = blockIdx.x * blockDim.x + threadIdx.x; i < tot;
         i += gridDim.x * blockDim.x) {
        int d = (i < E) ? ei32[(size_t)(E + i) << sh] : (i - E);
        if (d >= 0 && d < n) atomicAdd(&g_deg[d], 1);
    }
}

// ---------------- 3-phase exclusive scan ----------------------------------------
__global__ void scan_a(int n) {
    __shared__ int s[256];
    int b = blockIdx.x, t = threadIdx.x, i = b * 256 + t;
    s[t] = (i < n) ? g_deg[i] : 0;
    __syncthreads();
    #pragma unroll
    for (int d = 1; d < 256; d <<= 1) {
        int v = (t >= d) ? s[t - d] : 0;
        __syncthreads();
        s[t] += v;
        __syncthreads();
    }
    if (i < n) g_offs[i] = s[t];
    if (t == 255) g_part[b] = s[255];
}
__global__ void scan_b(int nb) {
    __shared__ int s[256];
    int t = threadIdx.x;
    s[t] = (t < nb) ? g_part[t] : 0;
    __syncthreads();
    #pragma unroll
    for (int d = 1; d < 256; d <<= 1) {
        int v = (t >= d) ? s[t - d] : 0;
        __syncthreads();
        s[t] += v;
        __syncthreads();
    }
    g_part[t] = (t > 0) ? s[t - 1] : 0;
}
__global__ void scan_c(int n) {
    int b = blockIdx.x, t = threadIdx.x, i = b * 256 + t;
    if (i >= n) return;
    int incl = g_offs[i] + g_part[b];
    g_offs[i] = incl - g_deg[i];
    if (i == n - 1) g_offs[n] = incl;
}

// ---------------- scatter edges into CSR-by-dst order (grid-stride) --------------
__global__ void scatter_k(const int* __restrict__ ei32, int E, int n) {
    int sh = g_shift;
    int tot = E + n;
    for (int i = blockIdx.x * blockDim.x + threadIdx.x; i < tot;
         i += gridDim.x * blockDim.x) {
        int s, d;
        if (i < E) { s = ei32[(size_t)i << sh]; d = ei32[(size_t)(E + i) << sh]; }
        else       { s = d = i - E; }
        if (d < 0 || d >= n) continue;
        int pos = g_offs[d] + atomicAdd(&g_cur[d], 1);
        g_src[pos] = s;
    }
}

// ---------------- fused softmax-attention aggregation ---------------------------
__global__ void agg_k(const float* __restrict__ att, const float* __restrict__ bias,
                      const float* __restrict__ bl, const float* __restrict__ br, int n) {
    int w = (blockIdx.x * blockDim.x + threadIdx.x) >> 5;
    int lane = threadIdx.x & 31;
    if (w >= n) return;
    int beg = g_offs[w], end = g_offs[w + 1];

    float4 r   = *(const float4*)&g_xr[(size_t)w * CH + lane * 4];
    float4 blv = *(const float4*)&bl[lane * 4];
    float4 brv = *(const float4*)&br[lane * 4];
    float4 av  = *(const float4*)&att[lane * 4];
    float4 rs = make_float4(r.x + blv.x + brv.x, r.y + blv.y + brv.y,
                            r.z + blv.z + brv.z, r.w + blv.w + brv.w);

    float a0 = 0.f, a1 = 0.f, a2 = 0.f, a3 = 0.f, den = 0.f;

    int p = beg;
    for (; p + 2 <= end; p += 2) {
        int s0 = g_src[p], s1 = g_src[p + 1];
        float4 x0 = *(const float4*)&g_xl[(size_t)s0 * CH + lane * 4];
        float4 x1 = *(const float4*)&g_xl[(size_t)s1 * CH + lane * 4];
        {
            float v0 = x0.x + rs.x; v0 = v0 > 0.f ? v0 : NEG_SLOPE * v0;
            float v1 = x0.y + rs.y; v1 = v1 > 0.f ? v1 : NEG_SLOPE * v1;
            float v2 = x0.z + rs.z; v2 = v2 > 0.f ? v2 : NEG_SLOPE * v2;
            float v3 = x0.w + rs.w; v3 = v3 > 0.f ? v3 : NEG_SLOPE * v3;
            float sc = fmaf(v0, av.x, fmaf(v1, av.y, fmaf(v2, av.z, v3 * av.w)));
            sc += __shfl_xor_sync(0xFFFFFFFFu, sc, 1);
            sc += __shfl_xor_sync(0xFFFFFFFFu, sc, 2);
            sc += __shfl_xor_sync(0xFFFFFFFFu, sc, 4);
            float e = __expf(sc);
            den += e;
            a0 = fmaf(e, x0.x, a0); a1 = fmaf(e, x0.y, a1);
            a2 = fmaf(e, x0.z, a2); a3 = fmaf(e, x0.w, a3);
        }
        {
            float v0 = x1.x + rs.x; v0 = v0 > 0.f ? v0 : NEG_SLOPE * v0;
            float v1 = x1.y + rs.y; v1 = v1 > 0.f ? v1 : NEG_SLOPE * v1;
            float v2 = x1.z + rs.z; v2 = v2 > 0.f ? v2 : NEG_SLOPE * v2;
            float v3 = x1.w + rs.w; v3 = v3 > 0.f ? v3 : NEG_SLOPE * v3;
            float sc = fmaf(v0, av.x, fmaf(v1, av.y, fmaf(v2, av.z, v3 * av.w)));
            sc += __shfl_xor_sync(0xFFFFFFFFu, sc, 1);
            sc += __shfl_xor_sync(0xFFFFFFFFu, sc, 2);
            sc += __shfl_xor_sync(0xFFFFFFFFu, sc, 4);
            float e = __expf(sc);
            den += e;
            a0 = fmaf(e, x1.x, a0); a1 = fmaf(e, x1.y, a1);
            a2 = fmaf(e, x1.z, a2); a3 = fmaf(e, x1.w, a3);
        }
    }
    if (p < end) {
        int s0 = g_src[p];
        float4 x0 = *(const float4*)&g_xl[(size_t)s0 * CH + lane * 4];
        float v0 = x0.x + rs.x; v0 = v0 > 0.f ? v0 : NEG_SLOPE * v0;
        float v1 = x0.y + rs.y; v1 = v1 > 0.f ? v1 : NEG_SLOPE * v1;
        float v2 = x0.z + rs.z; v2 = v2 > 0.f ? v2 : NEG_SLOPE * v2;
        float v3 = x0.w + rs.w; v3 = v3 > 0.f ? v3 : NEG_SLOPE * v3;
        float sc = fmaf(v0, av.x, fmaf(v1, av.y, fmaf(v2, av.z, v3 * av.w)));
        sc += __shfl_xor_sync(0xFFFFFFFFu, sc, 1);
        sc += __shfl_xor_sync(0xFFFFFFFFu, sc, 2);
        sc += __shfl_xor_sync(0xFFFFFFFFu, sc, 4);
        float e = __expf(sc);
        den += e;
        a0 = fmaf(e, x0.x, a0); a1 = fmaf(e, x0.y, a1);
        a2 = fmaf(e, x0.z, a2); a3 = fmaf(e, x0.w, a3);
    }

    float inv = 1.f / den;
    float4 b4 = *(const float4*)&bias[lane * 4];
    float4 o;
    o.x = fmaf(a0, inv, b4.x + blv.x);
    o.y = fmaf(a1, inv, b4.y + blv.y);
    o.z = fmaf(a2, inv, b4.z + blv.z);
    o.w = fmaf(a3, inv, b4.w + blv.w);
    *(float4*)&g_pre[(size_t)w * CH + lane * 4] = o;
}

// ---------------- BN stats -------------------------------------------------------
__global__ void stats_k(int n) {
    __shared__ float ss[256], qq[256];
    int t = threadIdx.x;
    int c = t & 127;
    int half = t >> 7;
    float s = 0.f, q = 0.f;
    for (int r = blockIdx.x * 2 + half; r < n; r += gridDim.x * 2) {
        float v = g_pre[(size_t)r * CH + c];
        s += v;
        q = fmaf(v, v, q);
    }
    ss[t] = s; qq[t] = q;
    __syncthreads();
    if (t < 128) {
        s = ss[t] + ss[t + 128];
        q = qq[t] + qq[t + 128];
        atomicAdd(&g_sum[c], s);
        atomicAdd(&g_sumsq[c], q);
    }
}

// ---------------- final: BN + residual + ELU (float4) ----------------------------
__global__ void final_k(const float* __restrict__ x,
                        const float* __restrict__ gamma,
                        const float* __restrict__ beta,
                        float* __restrict__ out, int n) {
    int i = blockIdx.x * blockDim.x + threadIdx.x;   // float4 index
    if (i >= n * 32) return;
    int c4 = i & 31;
    float invn = 1.f / (float)n;
    float4 p = ((const float4*)g_pre)[i];
    float4 xv = ((const float4*)x)[i];
    float4 gm = ((const float4*)gamma)[c4];
    float4 bt = ((const float4*)beta)[c4];
    float4 sm4 = ((const float4*)g_sum)[c4];
    float4 sq4 = ((const float4*)g_sumsq)[c4];
    float4 o;
    {
        float mu = sm4.x * invn, var = sq4.x * invn - mu * mu;
        float y = (p.x - mu) * rsqrtf(var + BN_EPS) * gm.x + bt.x + xv.x;
        o.x = (y > 0.f) ? y : (__expf(y) - 1.f);
    }
    {
        float mu = sm4.y * invn, var = sq4.y * invn - mu * mu;
        float y = (p.y - mu) * rsqrtf(var + BN_EPS) * gm.y + bt.y + xv.y;
        o.y = (y > 0.f) ? y : (__expf(y) - 1.f);
    }
    {
        float mu = sm4.z * invn, var = sq4.z * invn - mu * mu;
        float y = (p.z - mu) * rsqrtf(var + BN_EPS) * gm.z + bt.z + xv.z;
        o.z = (y > 0.f) ? y : (__expf(y) - 1.f);
    }
    {
        float mu = sm4.w * invn, var = sq4.w * invn - mu * mu;
        float y = (p.w - mu) * rsqrtf(var + BN_EPS) * gm.w + bt.w + xv.w;
        o.w = (y > 0.f) ? y : (__expf(y) - 1.f);
    }
    ((float4*)out)[i] = o;
}

// ---------------- launch ----------------------------------------------------------
extern "C" void kernel_launch(void* const* d_in, const int* in_sizes, int n_in,
                              void* d_out, int out_size) {
    const float* x     = (const float*)d_in[0];
    const int*   ei32  = (const int*)d_in[1];
    const float* Wl    = (const float*)d_in[2];
    const float* bl    = (const float*)d_in[3];
    const float* Wr    = (const float*)d_in[4];
    const float* br    = (const float*)d_in[5];
    const float* att   = (const float*)d_in[6];
    const float* bias  = (const float*)d_in[7];
    const float* gamma = (const float*)d_in[8];
    const float* beta  = (const float*)d_in[9];
    float*       out   = (float*)d_out;

    int n = in_sizes[0] / CH;          // 50000
    int E = in_sizes[1] / 2;           // 800000
    int nb = (n + 255) / 256;

    const int SMEM_GEMM = (2 * 64 + 2 * 128) * PADK * (int)sizeof(__nv_bfloat16);
    cudaFuncSetAttribute(gemm_mma_k, cudaFuncAttributeMaxDynamicSharedMemorySize, SMEM_GEMM);

    // fork/join: graph-build chain runs concurrently with GEMM chain.
    cudaStream_t s1;
    cudaStreamCreateWithFlags(&s1, cudaStreamNonBlocking);
    cudaEvent_t evFork, evJoin;
    cudaEventCreateWithFlags(&evFork, cudaEventDisableTiming);
    cudaEventCreateWithFlags(&evJoin, cudaEventDisableTiming);

    const int T = 256;
    init_k<<<nb, 256>>>(ei32);
    cudaEventRecord(evFork, 0);
    cudaStreamWaitEvent(s1, evFork, 0);

    // branch B (stream s1): CSR build
    hist_k<<<1184, T, 0, s1>>>(ei32, E, n);
    scan_a<<<nb, 256, 0, s1>>>(n);
    scan_b<<<1, 256, 0, s1>>>(nb);
    scan_c<<<nb, 256, 0, s1>>>(n);
    scatter_k<<<1184, T, 0, s1>>>(ei32, E, n);
    cudaEventRecord(evJoin, s1);

    // branch A (default stream): GEMM
    split_w_k<<<128, 256>>>(Wl, Wr);
    dim3 gg((n + 63) / 64, 2);
    gemm_mma_k<<<gg, 256, SMEM_GEMM>>>(x, n);

    cudaStreamWaitEvent(0, evJoin, 0);
    agg_k<<<((size_t)n * 32 + T - 1) / T, T>>>(att, bias, bl, br, n);
    stats_k<<<512, 256>>>(n);
    final_k<<<(n * 32 + T - 1) / T, T>>>(x, gamma, beta, out, n);

    cudaEventDestroy(evFork);
    cudaEventDestroy(evJoin);
    cudaStreamDestroy(s1);
}

// round 9
// speedup vs baseline: 2.8404x; 1.0342x over previous
#include <cuda_runtime.h>
#include <cuda_bf16.h>
#include <cuda_fp16.h>
#include <math.h>
#include <stdint.h>

#define N_NODES 50000
#define E_EDGES 800000
#define ETOT (E_EDGES + N_NODES)
#define CH 128
#define NEG_SLOPE 0.2f
#define BN_EPS 1e-5f
#define PADK 136   // bf16 per smem row (272B) -> conflict-free ldmatrix phases

// ---------------- scratch (static device globals; no allocations) -------------
__device__ __align__(16) __half g_xlh[(size_t)N_NODES * CH];   // fp16 gather payload
__device__ __align__(16) float g_xr[(size_t)N_NODES * CH];
__device__ __align__(16) float g_pre[(size_t)N_NODES * CH];
__device__ __align__(16) __nv_bfloat16 g_wh[256 * 128];    // [n=256][k=128]
__device__ __align__(16) __nv_bfloat16 g_wlo[256 * 128];
__device__ int   g_deg[N_NODES];
__device__ int   g_cur[N_NODES];
__device__ int   g_offs[N_NODES + 1];
__device__ int   g_src[ETOT];
__device__ int   g_part[256];
__device__ float g_sum[CH];
__device__ float g_sumsq[CH];
__device__ int   g_shift;   // 0: edge_index int32; 1: int64 (read low word)

// ---------------- init (+ dtype detect in block 0) ------------------------------
__global__ void init_k(const int* __restrict__ ei32) {
    int i = blockIdx.x * blockDim.x + threadIdx.x;
    if (i < N_NODES) { g_deg[i] = 0; g_cur[i] = 0; }
    if (i < CH) { g_sum[i] = 0.f; g_sumsq[i] = 0.f; }
    if (blockIdx.x == 0) {
        __shared__ int nz;
        if (threadIdx.x == 0) nz = 0;
        __syncthreads();
        if (ei32[2 * threadIdx.x + 1] != 0) atomicOr(&nz, 1);
        __syncthreads();
        if (threadIdx.x == 0) g_shift = nz ? 0 : 1;
    }
}

// ---------------- transpose+split W into B layout [n=256][k=128] ----------------
__global__ void split_w_k(const float* __restrict__ Wl, const float* __restrict__ Wr) {
    int i = blockIdx.x * blockDim.x + threadIdx.x;   // i = nc*128 + k
    if (i >= 256 * 128) return;
    int nc = i >> 7, k = i & 127;
    float v = (nc < 128) ? Wl[k * 128 + nc] : Wr[k * 128 + (nc - 128)];
    __nv_bfloat16 h = __float2bfloat16(v);
    g_wh[i] = h;
    g_wlo[i] = __float2bfloat16(v - __bfloat162float(h));
}

// ---------------- mma / ldmatrix wrappers ----------------------------------------
__device__ __forceinline__ void mma16816(float* c, const uint32_t* a, const uint32_t* b) {
    asm volatile(
        "mma.sync.aligned.m16n8k16.row.col.f32.bf16.bf16.f32 "
        "{%0,%1,%2,%3}, {%4,%5,%6,%7}, {%8,%9}, {%0,%1,%2,%3};"
        : "+f"(c[0]), "+f"(c[1]), "+f"(c[2]), "+f"(c[3])
        : "r"(a[0]), "r"(a[1]), "r"(a[2]), "r"(a[3]), "r"(b[0]), "r"(b[1]));
}
__device__ __forceinline__ uint32_t smem_u32(const void* p) {
    uint32_t a;
    asm("{ .reg .u64 t; cvta.to.shared.u64 t, %1; cvt.u32.u64 %0, t; }" : "=r"(a) : "l"(p));
    return a;
}
#define LDMX4(r0, r1, r2, r3, a) \
    asm volatile("ldmatrix.sync.aligned.m8n8.x4.shared.b16 {%0,%1,%2,%3}, [%4];" \
        : "=r"(r0), "=r"(r1), "=r"(r2), "=r"(r3) : "r"(a))

// ---------------- tensor-core GEMM via mma.sync + ldmatrix -----------------------
// grid (ceil(n/64), 2). by=0 -> W_l -> g_xlh (fp16) ; by=1 -> W_r -> g_xr (fp32).
// split precision: D = Ah*Bh + Ah*Bl + Al*Bh (fp32 accum).
__global__ void __launch_bounds__(256) gemm_mma_k(const float* __restrict__ x, int n) {
    extern __shared__ __nv_bfloat16 sm[];
    __nv_bfloat16* sAh = sm;                     //  64 x PADK
    __nv_bfloat16* sAl = sAh + 64 * PADK;        //  64 x PADK
    __nv_bfloat16* sBh = sAl + 64 * PADK;        // 128 x PADK
    __nv_bfloat16* sBl = sBh + 128 * PADK;       // 128 x PADK

    int t = threadIdx.x;
    int row0 = blockIdx.x * 64;
    int by = blockIdx.y;

    for (int l = t; l < 2048; l += 256) {
        int r = l >> 5, j = l & 31;
        float4 v = make_float4(0.f, 0.f, 0.f, 0.f);
        if (row0 + r < n) v = ((const float4*)x)[(size_t)(row0 + r) * 32 + j];
        __nv_bfloat16 h0 = __float2bfloat16(v.x), h1 = __float2bfloat16(v.y);
        __nv_bfloat16 h2 = __float2bfloat16(v.z), h3 = __float2bfloat16(v.w);
        __nv_bfloat162 hA = __halves2bfloat162(h0, h1), hB = __halves2bfloat162(h2, h3);
        __nv_bfloat162 lA = __halves2bfloat162(__float2bfloat16(v.x - __bfloat162float(h0)),
                                               __float2bfloat16(v.y - __bfloat162float(h1)));
        __nv_bfloat162 lB = __halves2bfloat162(__float2bfloat16(v.z - __bfloat162float(h2)),
                                               __float2bfloat16(v.w - __bfloat162float(h3)));
        *(uint2*)&sAh[r * PADK + j * 4] = make_uint2(*(uint32_t*)&hA, *(uint32_t*)&hB);
        *(uint2*)&sAl[r * PADK + j * 4] = make_uint2(*(uint32_t*)&lA, *(uint32_t*)&lB);
    }
    for (int l = t; l < 2048; l += 256) {
        int r = l >> 4, j = l & 15;
        *(uint4*)&sBh[r * PADK + j * 8] = ((const uint4*)g_wh)[(size_t)(by * 128 + r) * 16 + j];
        *(uint4*)&sBl[r * PADK + j * 8] = ((const uint4*)g_wlo)[(size_t)(by * 128 + r) * 16 + j];
    }
    __syncthreads();

    int warp = t >> 5, lane = t & 31;
    int rg = warp >> 2, cg = warp & 3;
    int lr = lane >> 2, lk = (lane & 3) * 2;

    uint32_t aRow = (uint32_t)(rg * 32 + (lane & 15));
    uint32_t aKof = (uint32_t)((lane >> 4) << 3);
    uint32_t aOff = (aRow * PADK + aKof) * 2;
    uint32_t ah_base = smem_u32(sAh) + aOff;
    uint32_t al_base = smem_u32(sAl) + aOff;
    uint32_t bRow = (uint32_t)(cg * 32 + (lane & 7) + ((lane >> 4) << 3));
    uint32_t bKof = (uint32_t)(((lane >> 3) & 1) << 3);
    uint32_t bOff = (bRow * PADK + bKof) * 2;
    uint32_t bh_base = smem_u32(sBh) + bOff;
    uint32_t bl_base = smem_u32(sBl) + bOff;
    const uint32_t MF_STEP = 16 * PADK * 2;

    float acc[2][4][4];
    #pragma unroll
    for (int mf = 0; mf < 2; mf++)
        #pragma unroll
        for (int nf = 0; nf < 4; nf++)
            #pragma unroll
            for (int q = 0; q < 4; q++) acc[mf][nf][q] = 0.f;

    #pragma unroll
    for (int ks = 0; ks < 8; ks++) {
        uint32_t ko = (uint32_t)ks * 32;
        uint32_t ah[2][4], al[2][4], bh[4][2], bl2[4][2];
        LDMX4(ah[0][0], ah[0][1], ah[0][2], ah[0][3], ah_base + ko);
        LDMX4(ah[1][0], ah[1][1], ah[1][2], ah[1][3], ah_base + MF_STEP + ko);
        LDMX4(al[0][0], al[0][1], al[0][2], al[0][3], al_base + ko);
        LDMX4(al[1][0], al[1][1], al[1][2], al[1][3], al_base + MF_STEP + ko);
        LDMX4(bh[0][0], bh[0][1], bh[1][0], bh[1][1], bh_base + ko);
        LDMX4(bh[2][0], bh[2][1], bh[3][0], bh[3][1], bh_base + MF_STEP + ko);
        LDMX4(bl2[0][0], bl2[0][1], bl2[1][0], bl2[1][1], bl_base + ko);
        LDMX4(bl2[2][0], bl2[2][1], bl2[3][0], bl2[3][1], bl_base + MF_STEP + ko);
        #pragma unroll
        for (int mf = 0; mf < 2; mf++)
            #pragma unroll
            for (int nf = 0; nf < 4; nf++) {
                mma16816(acc[mf][nf], ah[mf], bh[nf]);
                mma16816(acc[mf][nf], ah[mf], bl2[nf]);
                mma16816(acc[mf][nf], al[mf], bh[nf]);
            }
    }

    #pragma unroll
    for (int mf = 0; mf < 2; mf++) {
        int row = row0 + rg * 32 + mf * 16 + lr;
        #pragma unroll
        for (int nf = 0; nf < 4; nf++) {
            int col = cg * 32 + nf * 8 + lk;
            if (by == 0) {
                __half2 p0 = __floats2half2_rn(acc[mf][nf][0], acc[mf][nf][1]);
                __half2 p1 = __floats2half2_rn(acc[mf][nf][2], acc[mf][nf][3]);
                if (row < n)
                    *(uint32_t*)&g_xlh[(size_t)row * CH + col] = *(uint32_t*)&p0;
                if (row + 8 < n)
                    *(uint32_t*)&g_xlh[(size_t)(row + 8) * CH + col] = *(uint32_t*)&p1;
            } else {
                if (row < n)
                    *(float2*)&g_xr[(size_t)row * CH + col] =
                        make_float2(acc[mf][nf][0], acc[mf][nf][1]);
                if (row + 8 < n)
                    *(float2*)&g_xr[(size_t)(row + 8) * CH + col] =
                        make_float2(acc[mf][nf][2], acc[mf][nf][3]);
            }
        }
    }
}

// ---------------- degree histogram (grid-stride) ---------------------------------
__global__ void hist_k(const int* __restrict__ ei32, int E, int n) {
    int sh = g_shift;
    int tot = E + n;
    for (int i = blockIdx.x * blockDim.x + threadIdx.x; i < tot;
         i += gridDim.x * blockDim.x) {
        int d = (i < E) ? ei32[(size_t)(E + i) << sh] : (i - E);
        if (d >= 0 && d < n) atomicAdd(&g_deg[d], 1);
    }
}

// ---------------- 3-phase exclusive scan ----------------------------------------
__global__ void scan_a(int n) {
    __shared__ int s[256];
    int b = blockIdx.x, t = threadIdx.x, i = b * 256 + t;
    s[t] = (i < n) ? g_deg[i] : 0;
    __syncthreads();
    #pragma unroll
    for (int d = 1; d < 256; d <<= 1) {
        int v = (t >= d) ? s[t - d] : 0;
        __syncthreads();
        s[t] += v;
        __syncthreads();
    }
    if (i < n) g_offs[i] = s[t];
    if (t == 255) g_part[b] = s[255];
}
__global__ void scan_b(int nb) {
    __shared__ int s[256];
    int t = threadIdx.x;
    s[t] = (t < nb) ? g_part[t] : 0;
    __syncthreads();
    #pragma unroll
    for (int d = 1; d < 256; d <<= 1) {
        int v = (t >= d) ? s[t - d] : 0;
        __syncthreads();
        s[t] += v;
        __syncthreads();
    }
    g_part[t] = (t > 0) ? s[t - 1] : 0;
}
__global__ void scan_c(int n) {
    int b = blockIdx.x, t = threadIdx.x, i = b * 256 + t;
    if (i >= n) return;
    int incl = g_offs[i] + g_part[b];
    g_offs[i] = incl - g_deg[i];
    if (i == n - 1) g_offs[n] = incl;
}

// ---------------- scatter edges into CSR-by-dst order (grid-stride) --------------
__global__ void scatter_k(const int* __restrict__ ei32, int E, int n) {
    int sh = g_shift;
    int tot = E + n;
    for (int i = blockIdx.x * blockDim.x + threadIdx.x; i < tot;
         i += gridDim.x * blockDim.x) {
        int s, d;
        if (i < E) { s = ei32[(size_t)i << sh]; d = ei32[(size_t)(E + i) << sh]; }
        else       { s = d = i - E; }
        if (d < 0 || d >= n) continue;
        int pos = g_offs[d] + atomicAdd(&g_cur[d], 1);
        g_src[pos] = s;
    }
}

// ---------------- per-edge helper -------------------------------------------------
__device__ __forceinline__ void edge_acc(uint2 u, float4 rs, float4 av,
                                         float& a0, float& a1, float& a2, float& a3,
                                         float& den) {
    float2 f01 = __half22float2(*(__half2*)&u.x);
    float2 f23 = __half22float2(*(__half2*)&u.y);
    float v0 = f01.x + rs.x; v0 = v0 > 0.f ? v0 : NEG_SLOPE * v0;
    float v1 = f01.y + rs.y; v1 = v1 > 0.f ? v1 : NEG_SLOPE * v1;
    float v2 = f23.x + rs.z; v2 = v2 > 0.f ? v2 : NEG_SLOPE * v2;
    float v3 = f23.y + rs.w; v3 = v3 > 0.f ? v3 : NEG_SLOPE * v3;
    float sc = fmaf(v0, av.x, fmaf(v1, av.y, fmaf(v2, av.z, v3 * av.w)));
    sc += __shfl_xor_sync(0xFFFFFFFFu, sc, 1);
    sc += __shfl_xor_sync(0xFFFFFFFFu, sc, 2);
    sc += __shfl_xor_sync(0xFFFFFFFFu, sc, 4);
    float e = __expf(sc);
    den += e;
    a0 = fmaf(e, f01.x, a0); a1 = fmaf(e, f01.y, a1);
    a2 = fmaf(e, f23.x, a2); a3 = fmaf(e, f23.y, a3);
}

// ---------------- fused softmax-attention aggregation + BN stats -----------------
__global__ void agg_k(const float* __restrict__ att, const float* __restrict__ bias,
                      const float* __restrict__ bl, const float* __restrict__ br, int n) {
    __shared__ float ss[128], qq[128];
    int t = threadIdx.x;
    if (t < 128) { ss[t] = 0.f; qq[t] = 0.f; }
    __syncthreads();

    int w = (blockIdx.x * blockDim.x + t) >> 5;
    int lane = t & 31;

    if (w < n) {
        int beg = g_offs[w], end = g_offs[w + 1];
        float4 r   = *(const float4*)&g_xr[(size_t)w * CH + lane * 4];
        float4 blv = *(const float4*)&bl[lane * 4];
        float4 brv = *(const float4*)&br[lane * 4];
        float4 av  = *(const float4*)&att[lane * 4];
        float4 rs = make_float4(r.x + blv.x + brv.x, r.y + blv.y + brv.y,
                                r.z + blv.z + brv.z, r.w + blv.w + brv.w);

        float a0 = 0.f, a1 = 0.f, a2 = 0.f, a3 = 0.f, den = 0.f;
        int p = beg;
        for (; p + 4 <= end; p += 4) {
            int s0 = g_src[p], s1 = g_src[p + 1], s2 = g_src[p + 2], s3 = g_src[p + 3];
            uint2 u0 = *(const uint2*)&g_xlh[(size_t)s0 * CH + lane * 4];
            uint2 u1 = *(const uint2*)&g_xlh[(size_t)s1 * CH + lane * 4];
            uint2 u2 = *(const uint2*)&g_xlh[(size_t)s2 * CH + lane * 4];
            uint2 u3 = *(const uint2*)&g_xlh[(size_t)s3 * CH + lane * 4];
            edge_acc(u0, rs, av, a0, a1, a2, a3, den);
            edge_acc(u1, rs, av, a0, a1, a2, a3, den);
            edge_acc(u2, rs, av, a0, a1, a2, a3, den);
            edge_acc(u3, rs, av, a0, a1, a2, a3, den);
        }
        for (; p < end; p++) {
            uint2 u0 = *(const uint2*)&g_xlh[(size_t)g_src[p] * CH + lane * 4];
            edge_acc(u0, rs, av, a0, a1, a2, a3, den);
        }

        float inv = 1.f / den;
        float4 b4 = *(const float4*)&bias[lane * 4];
        float4 o;
        o.x = fmaf(a0, inv, b4.x + blv.x);
        o.y = fmaf(a1, inv, b4.y + blv.y);
        o.z = fmaf(a2, inv, b4.z + blv.z);
        o.w = fmaf(a3, inv, b4.w + blv.w);
        *(float4*)&g_pre[(size_t)w * CH + lane * 4] = o;

        int c = lane * 4;
        atomicAdd(&ss[c + 0], o.x); atomicAdd(&qq[c + 0], o.x * o.x);
        atomicAdd(&ss[c + 1], o.y); atomicAdd(&qq[c + 1], o.y * o.y);
        atomicAdd(&ss[c + 2], o.z); atomicAdd(&qq[c + 2], o.z * o.z);
        atomicAdd(&ss[c + 3], o.w); atomicAdd(&qq[c + 3], o.w * o.w);
    }
    __syncthreads();
    if (t < 128) {
        atomicAdd(&g_sum[t], ss[t]);
        atomicAdd(&g_sumsq[t], qq[t]);
    }
}

// ---------------- final: BN + residual + ELU (float4) ----------------------------
__global__ void final_k(const float* __restrict__ x,
                        const float* __restrict__ gamma,
                        const float* __restrict__ beta,
                        float* __restrict__ out, int n) {
    int i = blockIdx.x * blockDim.x + threadIdx.x;   // float4 index
    if (i >= n * 32) return;
    int c4 = i & 31;
    float invn = 1.f / (float)n;
    float4 p = ((const float4*)g_pre)[i];
    float4 xv = ((const float4*)x)[i];
    float4 gm = ((const float4*)gamma)[c4];
    float4 bt = ((const float4*)beta)[c4];
    float4 sm4 = ((const float4*)g_sum)[c4];
    float4 sq4 = ((const float4*)g_sumsq)[c4];
    float4 o;
    {
        float mu = sm4.x * invn, var = sq4.x * invn - mu * mu;
        float y = (p.x - mu) * rsqrtf(var + BN_EPS) * gm.x + bt.x + xv.x;
        o.x = (y > 0.f) ? y : (__expf(y) - 1.f);
    }
    {
        float mu = sm4.y * invn, var = sq4.y * invn - mu * mu;
        float y = (p.y - mu) * rsqrtf(var + BN_EPS) * gm.y + bt.y + xv.y;
        o.y = (y > 0.f) ? y : (__expf(y) - 1.f);
    }
    {
        float mu = sm4.z * invn, var = sq4.z * invn - mu * mu;
        float y = (p.z - mu) * rsqrtf(var + BN_EPS) * gm.z + bt.z + xv.z;
        o.z = (y > 0.f) ? y : (__expf(y) - 1.f);
    }
    {
        float mu = sm4.w * invn, var = sq4.w * invn - mu * mu;
        float y = (p.w - mu) * rsqrtf(var + BN_EPS) * gm.w + bt.w + xv.w;
        o.w = (y > 0.f) ? y : (__expf(y) - 1.f);
    }
    ((float4*)out)[i] = o;
}

// ---------------- launch ----------------------------------------------------------
extern "C" void kernel_launch(void* const* d_in, const int* in_sizes, int n_in,
                              void* d_out, int out_size) {
    const float* x     = (const float*)d_in[0];
    const int*   ei32  = (const int*)d_in[1];
    const float* Wl    = (const float*)d_in[2];
    const float* bl    = (const float*)d_in[3];
    const float* Wr    = (const float*)d_in[4];
    const float* br    = (const float*)d_in[5];
    const float* att   = (const float*)d_in[6];
    const float* bias  = (const float*)d_in[7];
    const float* gamma = (const float*)d_in[8];
    const float* beta  = (const float*)d_in[9];
    float*       out   = (float*)d_out;

    int n = in_sizes[0] / CH;          // 50000
    int E = in_sizes[1] / 2;           // 800000
    int nb = (n + 255) / 256;

    const int SMEM_GEMM = (2 * 64 + 2 * 128) * PADK * (int)sizeof(__nv_bfloat16);
    cudaFuncSetAttribute(gemm_mma_k, cudaFuncAttributeMaxDynamicSharedMemorySize, SMEM_GEMM);

    cudaStream_t s1;
    cudaStreamCreateWithFlags(&s1, cudaStreamNonBlocking);
    cudaEvent_t evFork, evJoin;
    cudaEventCreateWithFlags(&evFork, cudaEventDisableTiming);
    cudaEventCreateWithFlags(&evJoin, cudaEventDisableTiming);

    const int T = 256;
    init_k<<<nb, 256>>>(ei32);
    cudaEventRecord(evFork, 0);
    cudaStreamWaitEvent(s1, evFork, 0);

    // branch B (stream s1): CSR build
    hist_k<<<1184, T, 0, s1>>>(ei32, E, n);
    scan_a<<<nb, 256, 0, s1>>>(n);
    scan_b<<<1, 256, 0, s1>>>(nb);
    scan_c<<<nb, 256, 0, s1>>>(n);
    scatter_k<<<1184, T, 0, s1>>>(ei32, E, n);
    cudaEventRecord(evJoin, s1);

    // branch A (default stream): GEMM
    split_w_k<<<128, 256>>>(Wl, Wr);
    dim3 gg((n + 63) / 64, 2);
    gemm_mma_k<<<gg, 256, SMEM_GEMM>>>(x, n);

    cudaStreamWaitEvent(0, evJoin, 0);
    agg_k<<<((size_t)n * 32 + T - 1) / T, T>>>(att, bias, bl, br, n);
    final_k<<<(n * 32 + T - 1) / T, T>>>(x, gamma, beta, out, n);

    cudaEventDestroy(evFork);
    cudaEventDestroy(evJoin);
    cudaStreamDestroy(s1);
}

// round 10
// speedup vs baseline: 3.1008x; 1.0917x over previous
#include <cuda_runtime.h>
#include <cuda_bf16.h>
#include <cuda_fp16.h>
#include <math.h>
#include <stdint.h>

#define N_NODES 50000
#define E_EDGES 800000
#define ETOT (E_EDGES + N_NODES)
#define CH 128
#define NEG_SLOPE 0.2f
#define BN_EPS 1e-5f
#define PADK 136   // bf16 per smem row (272B) -> conflict-free ldmatrix phases

// ---------------- scratch (static device globals; no allocations) -------------
__device__ __align__(16) __half g_xlh[(size_t)N_NODES * CH];   // fp16 gather payload
__device__ __align__(16) float g_xr[(size_t)N_NODES * CH];
__device__ __align__(16) float g_pre[(size_t)N_NODES * CH];
// fragment-major packed weights: [group g=nc/8 (32)][ks (8)][lane (32)] -> uint2
__device__ __align__(16) uint2 g_wph[32 * 8 * 32];
__device__ __align__(16) uint2 g_wpl[32 * 8 * 32];
__device__ int   g_deg[N_NODES];
__device__ int   g_cur[N_NODES];
__device__ int   g_offs[N_NODES + 1];
__device__ int   g_src[ETOT];
__device__ int   g_part[256];
__device__ float g_sum[CH];
__device__ float g_sumsq[CH];
__device__ int   g_shift;   // 0: edge_index int32; 1: int64 (read low word)

// ---------------- init (+ dtype detect in block 0) ------------------------------
__global__ void init_k(const int* __restrict__ ei32) {
    int i = blockIdx.x * blockDim.x + threadIdx.x;
    if (i < N_NODES) { g_deg[i] = 0; g_cur[i] = 0; }
    if (i < CH) { g_sum[i] = 0.f; g_sumsq[i] = 0.f; }
    if (blockIdx.x == 0) {
        __shared__ int nz;
        if (threadIdx.x == 0) nz = 0;
        __syncthreads();
        if (ei32[2 * threadIdx.x + 1] != 0) atomicOr(&nz, 1);
        __syncthreads();
        if (threadIdx.x == 0) g_shift = nz ? 0 : 1;
    }
}

// ---------------- pack W into B-fragment-major hi/lo layout ----------------------
// fragment for col-group g, k-step ks, lane l:
//   n = g*8 + (l>>2), k0 = ks*16 + (l&3)*2
//   uint2.x = bf16{W[k0][n], W[k0+1][n]}, uint2.y = bf16{W[k0+8][n], W[k0+9][n]}
__global__ void pack_w_k(const float* __restrict__ Wl, const float* __restrict__ Wr) {
    int idx = blockIdx.x * blockDim.x + threadIdx.x;
    if (idx >= 8192) return;
    int lane = idx & 31, ks = (idx >> 5) & 7, g = idx >> 8;
    int nc = g * 8 + (lane >> 2);
    int k0 = ks * 16 + (lane & 3) * 2;
    const float* W = (nc < 128) ? (Wl + nc) : (Wr + nc - 128);
    float w0 = W[(size_t)k0 * 128];
    float w1 = W[(size_t)(k0 + 1) * 128];
    float w2 = W[(size_t)(k0 + 8) * 128];
    float w3 = W[(size_t)(k0 + 9) * 128];
    __nv_bfloat16 h0 = __float2bfloat16(w0), h1 = __float2bfloat16(w1);
    __nv_bfloat16 h2 = __float2bfloat16(w2), h3 = __float2bfloat16(w3);
    __nv_bfloat162 ph0 = __halves2bfloat162(h0, h1), ph1 = __halves2bfloat162(h2, h3);
    __nv_bfloat162 pl0 = __halves2bfloat162(__float2bfloat16(w0 - __bfloat162float(h0)),
                                            __float2bfloat16(w1 - __bfloat162float(h1)));
    __nv_bfloat162 pl1 = __halves2bfloat162(__float2bfloat16(w2 - __bfloat162float(h2)),
                                            __float2bfloat16(w3 - __bfloat162float(h3)));
    g_wph[idx] = make_uint2(*(uint32_t*)&ph0, *(uint32_t*)&ph1);
    g_wpl[idx] = make_uint2(*(uint32_t*)&pl0, *(uint32_t*)&pl1);
}

// ---------------- mma / ldmatrix wrappers ----------------------------------------
__device__ __forceinline__ void mma16816(float* c, const uint32_t* a, const uint32_t* b) {
    asm volatile(
        "mma.sync.aligned.m16n8k16.row.col.f32.bf16.bf16.f32 "
        "{%0,%1,%2,%3}, {%4,%5,%6,%7}, {%8,%9}, {%0,%1,%2,%3};"
        : "+f"(c[0]), "+f"(c[1]), "+f"(c[2]), "+f"(c[3])
        : "r"(a[0]), "r"(a[1]), "r"(a[2]), "r"(a[3]), "r"(b[0]), "r"(b[1]));
}
__device__ __forceinline__ uint32_t smem_u32(const void* p) {
    uint32_t a;
    asm("{ .reg .u64 t; cvta.to.shared.u64 t, %1; cvt.u32.u64 %0, t; }" : "=r"(a) : "l"(p));
    return a;
}
#define LDMX4(r0, r1, r2, r3, a) \
    asm volatile("ldmatrix.sync.aligned.m8n8.x4.shared.b16 {%0,%1,%2,%3}, [%4];" \
        : "=r"(r0), "=r"(r1), "=r"(r2), "=r"(r3) : "r"(a))

// ---------------- tensor-core GEMM: A in smem (ldmatrix), B from packed gmem -----
// grid (ceil(n/64), 2). by=0 -> W_l -> g_xlh (fp16) ; by=1 -> W_r -> g_xr (fp32).
// split precision: D = Ah*Bh + Ah*Bl + Al*Bh (fp32 accum).
__global__ void __launch_bounds__(256, 3) gemm_mma_k(const float* __restrict__ x, int n) {
    extern __shared__ __nv_bfloat16 sm[];
    __nv_bfloat16* sAh = sm;                     //  64 x PADK
    __nv_bfloat16* sAl = sAh + 64 * PADK;        //  64 x PADK

    int t = threadIdx.x;
    int row0 = blockIdx.x * 64;
    int by = blockIdx.y;

    // stage A: read fp32 x, split hi/lo in registers; 64 rows x 32 float4
    for (int l = t; l < 2048; l += 256) {
        int r = l >> 5, j = l & 31;
        float4 v = make_float4(0.f, 0.f, 0.f, 0.f);
        if (row0 + r < n) v = ((const float4*)x)[(size_t)(row0 + r) * 32 + j];
        __nv_bfloat16 h0 = __float2bfloat16(v.x), h1 = __float2bfloat16(v.y);
        __nv_bfloat16 h2 = __float2bfloat16(v.z), h3 = __float2bfloat16(v.w);
        __nv_bfloat162 hA = __halves2bfloat162(h0, h1), hB = __halves2bfloat162(h2, h3);
        __nv_bfloat162 lA = __halves2bfloat162(__float2bfloat16(v.x - __bfloat162float(h0)),
                                               __float2bfloat16(v.y - __bfloat162float(h1)));
        __nv_bfloat162 lB = __halves2bfloat162(__float2bfloat16(v.z - __bfloat162float(h2)),
                                               __float2bfloat16(v.w - __bfloat162float(h3)));
        *(uint2*)&sAh[r * PADK + j * 4] = make_uint2(*(uint32_t*)&hA, *(uint32_t*)&hB);
        *(uint2*)&sAl[r * PADK + j * 4] = make_uint2(*(uint32_t*)&lA, *(uint32_t*)&lB);
    }
    __syncthreads();

    int warp = t >> 5, lane = t & 31;
    int rg = warp >> 2, cg = warp & 3;
    int lr = lane >> 2, lk = (lane & 3) * 2;

    uint32_t aRow = (uint32_t)(rg * 32 + (lane & 15));
    uint32_t aKof = (uint32_t)((lane >> 4) << 3);
    uint32_t aOff = (aRow * PADK + aKof) * 2;
    uint32_t ah_base = smem_u32(sAh) + aOff;
    uint32_t al_base = smem_u32(sAl) + aOff;
    const uint32_t MF_STEP = 16 * PADK * 2;

    // packed-B base index: group g0 = by*16 + cg*4 ; index = ((g)*8+ks)*32 + lane
    int bbase = (by * 16 + cg * 4) * 256 + lane;

    float acc[2][4][4];
    #pragma unroll
    for (int mf = 0; mf < 2; mf++)
        #pragma unroll
        for (int nf = 0; nf < 4; nf++)
            #pragma unroll
            for (int q = 0; q < 4; q++) acc[mf][nf][q] = 0.f;

    #pragma unroll
    for (int ks = 0; ks < 8; ks++) {
        uint32_t ko = (uint32_t)ks * 32;
        uint32_t ah[2][4], al[2][4];
        LDMX4(ah[0][0], ah[0][1], ah[0][2], ah[0][3], ah_base + ko);
        LDMX4(ah[1][0], ah[1][1], ah[1][2], ah[1][3], ah_base + MF_STEP + ko);
        LDMX4(al[0][0], al[0][1], al[0][2], al[0][3], al_base + ko);
        LDMX4(al[1][0], al[1][1], al[1][2], al[1][3], al_base + MF_STEP + ko);
        #pragma unroll
        for (int nf = 0; nf < 4; nf++) {
            uint2 bh = g_wph[bbase + nf * 256 + ks * 32];
            uint2 bl = g_wpl[bbase + nf * 256 + ks * 32];
            uint32_t bhv[2] = {bh.x, bh.y};
            uint32_t blv[2] = {bl.x, bl.y};
            #pragma unroll
            for (int mf = 0; mf < 2; mf++) {
                mma16816(acc[mf][nf], ah[mf], bhv);
                mma16816(acc[mf][nf], ah[mf], blv);
                mma16816(acc[mf][nf], al[mf], bhv);
            }
        }
    }

    #pragma unroll
    for (int mf = 0; mf < 2; mf++) {
        int row = row0 + rg * 32 + mf * 16 + lr;
        #pragma unroll
        for (int nf = 0; nf < 4; nf++) {
            int col = cg * 32 + nf * 8 + lk;
            if (by == 0) {
                __half2 p0 = __floats2half2_rn(acc[mf][nf][0], acc[mf][nf][1]);
                __half2 p1 = __floats2half2_rn(acc[mf][nf][2], acc[mf][nf][3]);
                if (row < n)
                    *(uint32_t*)&g_xlh[(size_t)row * CH + col] = *(uint32_t*)&p0;
                if (row + 8 < n)
                    *(uint32_t*)&g_xlh[(size_t)(row + 8) * CH + col] = *(uint32_t*)&p1;
            } else {
                if (row < n)
                    *(float2*)&g_xr[(size_t)row * CH + col] =
                        make_float2(acc[mf][nf][0], acc[mf][nf][1]);
                if (row + 8 < n)
                    *(float2*)&g_xr[(size_t)(row + 8) * CH + col] =
                        make_float2(acc[mf][nf][2], acc[mf][nf][3]);
            }
        }
    }
}

// ---------------- degree histogram (grid-stride) ---------------------------------
__global__ void hist_k(const int* __restrict__ ei32, int E, int n) {
    int sh = g_shift;
    int tot = E + n;
    for (int i = blockIdx.x * blockDim.x + threadIdx.x; i < tot;
         i += gridDim.x * blockDim.x) {
        int d = (i < E) ? ei32[(size_t)(E + i) << sh] : (i - E);
        if (d >= 0 && d < n) atomicAdd(&g_deg[d], 1);
    }
}

// ---------------- 2-phase exclusive scan ----------------------------------------
__global__ void scan_a(int n) {
    __shared__ int s[256];
    int b = blockIdx.x, t = threadIdx.x, i = b * 256 + t;
    s[t] = (i < n) ? g_deg[i] : 0;
    __syncthreads();
    #pragma unroll
    for (int d = 1; d < 256; d <<= 1) {
        int v = (t >= d) ? s[t - d] : 0;
        __syncthreads();
        s[t] += v;
        __syncthreads();
    }
    if (i < n) g_offs[i] = s[t];
    if (t == 255) g_part[b] = s[255];
}
// each block warp-reduces its own prefix of g_part (<=256 ints), then fixes up
__global__ void scan_c(int n) {
    __shared__ int prefix;
    int b = blockIdx.x, t = threadIdx.x;
    if (t < 32) {
        int s = 0;
        for (int i = t; i < b; i += 32) s += g_part[i];
        #pragma unroll
        for (int o = 16; o; o >>= 1) s += __shfl_xor_sync(0xFFFFFFFFu, s, o);
        if (t == 0) prefix = s;
    }
    __syncthreads();
    int i = b * 256 + t;
    if (i >= n) return;
    int incl = g_offs[i] + prefix;
    g_offs[i] = incl - g_deg[i];
    if (i == n - 1) g_offs[n] = incl;
}

// ---------------- scatter edges into CSR-by-dst order (grid-stride) --------------
__global__ void scatter_k(const int* __restrict__ ei32, int E, int n) {
    int sh = g_shift;
    int tot = E + n;
    for (int i = blockIdx.x * blockDim.x + threadIdx.x; i < tot;
         i += gridDim.x * blockDim.x) {
        int s, d;
        if (i < E) { s = ei32[(size_t)i << sh]; d = ei32[(size_t)(E + i) << sh]; }
        else       { s = d = i - E; }
        if (d < 0 || d >= n) continue;
        int pos = g_offs[d] + atomicAdd(&g_cur[d], 1);
        g_src[pos] = s;
    }
}

// ---------------- per-edge helper -------------------------------------------------
__device__ __forceinline__ void edge_acc(uint2 u, float4 rs, float4 av,
                                         float& a0, float& a1, float& a2, float& a3,
                                         float& den) {
    float2 f01 = __half22float2(*(__half2*)&u.x);
    float2 f23 = __half22float2(*(__half2*)&u.y);
    float v0 = f01.x + rs.x; v0 = v0 > 0.f ? v0 : NEG_SLOPE * v0;
    float v1 = f01.y + rs.y; v1 = v1 > 0.f ? v1 : NEG_SLOPE * v1;
    float v2 = f23.x + rs.z; v2 = v2 > 0.f ? v2 : NEG_SLOPE * v2;
    float v3 = f23.y + rs.w; v3 = v3 > 0.f ? v3 : NEG_SLOPE * v3;
    float sc = fmaf(v0, av.x, fmaf(v1, av.y, fmaf(v2, av.z, v3 * av.w)));
    sc += __shfl_xor_sync(0xFFFFFFFFu, sc, 1);
    sc += __shfl_xor_sync(0xFFFFFFFFu, sc, 2);
    sc += __shfl_xor_sync(0xFFFFFFFFu, sc, 4);
    float e = __expf(sc);
    den += e;
    a0 = fmaf(e, f01.x, a0); a1 = fmaf(e, f01.y, a1);
    a2 = fmaf(e, f23.x, a2); a3 = fmaf(e, f23.y, a3);
}

// ---------------- fused softmax-attention aggregation + BN stats -----------------
__global__ void agg_k(const float* __restrict__ att, const float* __restrict__ bias,
                      const float* __restrict__ bl, const float* __restrict__ br, int n) {
    __shared__ float ss[128], qq[128];
    int t = threadIdx.x;
    if (t < 128) { ss[t] = 0.f; qq[t] = 0.f; }
    __syncthreads();

    int w = (blockIdx.x * blockDim.x + t) >> 5;
    int lane = t & 31;

    if (w < n) {
        int beg = g_offs[w], end = g_offs[w + 1];
        float4 r   = *(const float4*)&g_xr[(size_t)w * CH + lane * 4];
        float4 blv = *(const float4*)&bl[lane * 4];
        float4 brv = *(const float4*)&br[lane * 4];
        float4 av  = *(const float4*)&att[lane * 4];
        float4 rs = make_float4(r.x + blv.x + brv.x, r.y + blv.y + brv.y,
                                r.z + blv.z + brv.z, r.w + blv.w + brv.w);

        float a0 = 0.f, a1 = 0.f, a2 = 0.f, a3 = 0.f, den = 0.f;
        int p = beg;
        for (; p + 4 <= end; p += 4) {
            int s0 = g_src[p], s1 = g_src[p + 1], s2 = g_src[p + 2], s3 = g_src[p + 3];
            uint2 u0 = *(const uint2*)&g_xlh[(size_t)s0 * CH + lane * 4];
            uint2 u1 = *(const uint2*)&g_xlh[(size_t)s1 * CH + lane * 4];
            uint2 u2 = *(const uint2*)&g_xlh[(size_t)s2 * CH + lane * 4];
            uint2 u3 = *(const uint2*)&g_xlh[(size_t)s3 * CH + lane * 4];
            edge_acc(u0, rs, av, a0, a1, a2, a3, den);
            edge_acc(u1, rs, av, a0, a1, a2, a3, den);
            edge_acc(u2, rs, av, a0, a1, a2, a3, den);
            edge_acc(u3, rs, av, a0, a1, a2, a3, den);
        }
        for (; p < end; p++) {
            uint2 u0 = *(const uint2*)&g_xlh[(size_t)g_src[p] * CH + lane * 4];
            edge_acc(u0, rs, av, a0, a1, a2, a3, den);
        }

        float inv = 1.f / den;
        float4 b4 = *(const float4*)&bias[lane * 4];
        float4 o;
        o.x = fmaf(a0, inv, b4.x + blv.x);
        o.y = fmaf(a1, inv, b4.y + blv.y);
        o.z = fmaf(a2, inv, b4.z + blv.z);
        o.w = fmaf(a3, inv, b4.w + blv.w);
        *(float4*)&g_pre[(size_t)w * CH + lane * 4] = o;

        int c = lane * 4;
        atomicAdd(&ss[c + 0], o.x); atomicAdd(&qq[c + 0], o.x * o.x);
        atomicAdd(&ss[c + 1], o.y); atomicAdd(&qq[c + 1], o.y * o.y);
        atomicAdd(&ss[c + 2], o.z); atomicAdd(&qq[c + 2], o.z * o.z);
        atomicAdd(&ss[c + 3], o.w); atomicAdd(&qq[c + 3], o.w * o.w);
    }
    __syncthreads();
    if (t < 128) {
        atomicAdd(&g_sum[t], ss[t]);
        atomicAdd(&g_sumsq[t], qq[t]);
    }
}

// ---------------- final: BN + residual + ELU (float4) ----------------------------
__global__ void final_k(const float* __restrict__ x,
                        const float* __restrict__ gamma,
                        const float* __restrict__ beta,
                        float* __restrict__ out, int n) {
    int i = blockIdx.x * blockDim.x + threadIdx.x;   // float4 index
    if (i >= n * 32) return;
    int c4 = i & 31;
    float invn = 1.f / (float)n;
    float4 p = ((const float4*)g_pre)[i];
    float4 xv = ((const float4*)x)[i];
    float4 gm = ((const float4*)gamma)[c4];
    float4 bt = ((const float4*)beta)[c4];
    float4 sm4 = ((const float4*)g_sum)[c4];
    float4 sq4 = ((const float4*)g_sumsq)[c4];
    float4 o;
    {
        float mu = sm4.x * invn, var = sq4.x * invn - mu * mu;
        float y = (p.x - mu) * rsqrtf(var + BN_EPS) * gm.x + bt.x + xv.x;
        o.x = (y > 0.f) ? y : (__expf(y) - 1.f);
    }
    {
        float mu = sm4.y * invn, var = sq4.y * invn - mu * mu;
        float y = (p.y - mu) * rsqrtf(var + BN_EPS) * gm.y + bt.y + xv.y;
        o.y = (y > 0.f) ? y : (__expf(y) - 1.f);
    }
    {
        float mu = sm4.z * invn, var = sq4.z * invn - mu * mu;
        float y = (p.z - mu) * rsqrtf(var + BN_EPS) * gm.z + bt.z + xv.z;
        o.z = (y > 0.f) ? y : (__expf(y) - 1.f);
    }
    {
        float mu = sm4.w * invn, var = sq4.w * invn - mu * mu;
        float y = (p.w - mu) * rsqrtf(var + BN_EPS) * gm.w + bt.w + xv.w;
        o.w = (y > 0.f) ? y : (__expf(y) - 1.f);
    }
    ((float4*)out)[i] = o;
}

// ---------------- launch ----------------------------------------------------------
extern "C" void kernel_launch(void* const* d_in, const int* in_sizes, int n_in,
                              void* d_out, int out_size) {
    const float* x     = (const float*)d_in[0];
    const int*   ei32  = (const int*)d_in[1];
    const float* Wl    = (const float*)d_in[2];
    const float* bl    = (const float*)d_in[3];
    const float* Wr    = (const float*)d_in[4];
    const float* br    = (const float*)d_in[5];
    const float* att   = (const float*)d_in[6];
    const float* bias  = (const float*)d_in[7];
    const float* gamma = (const float*)d_in[8];
    const float* beta  = (const float*)d_in[9];
    float*       out   = (float*)d_out;

    int n = in_sizes[0] / CH;          // 50000
    int E = in_sizes[1] / 2;           // 800000
    int nb = (n + 255) / 256;

    const int SMEM_GEMM = 2 * 64 * PADK * (int)sizeof(__nv_bfloat16);  // 34816
    cudaFuncSetAttribute(gemm_mma_k, cudaFuncAttributeMaxDynamicSharedMemorySize, SMEM_GEMM);

    cudaStream_t s1;
    cudaStreamCreateWithFlags(&s1, cudaStreamNonBlocking);
    cudaEvent_t evFork, evJoin;
    cudaEventCreateWithFlags(&evFork, cudaEventDisableTiming);
    cudaEventCreateWithFlags(&evJoin, cudaEventDisableTiming);

    const int T = 256;
    init_k<<<nb, 256>>>(ei32);
    cudaEventRecord(evFork, 0);
    cudaStreamWaitEvent(s1, evFork, 0);

    // branch B (stream s1): CSR build
    hist_k<<<1184, T, 0, s1>>>(ei32, E, n);
    scan_a<<<nb, 256, 0, s1>>>(n);
    scan_c<<<nb, 256, 0, s1>>>(n);
    scatter_k<<<1184, T, 0, s1>>>(ei32, E, n);
    cudaEventRecord(evJoin, s1);

    // branch A (default stream): GEMM
    pack_w_k<<<32, 256>>>(Wl, Wr);
    dim3 gg((n + 63) / 64, 2);
    gemm_mma_k<<<gg, 256, SMEM_GEMM>>>(x, n);

    cudaStreamWaitEvent(0, evJoin, 0);
    agg_k<<<((size_t)n * 32 + T - 1) / T, T>>>(att, bias, bl, br, n);
    final_k<<<(n * 32 + T - 1) / T, T>>>(x, gamma, beta, out, n);

    cudaEventDestroy(evFork);
    cudaEventDestroy(evJoin);
    cudaStreamDestroy(s1);
}